// round 7
// baseline (speedup 1.0000x reference)
#include <cuda_runtime.h>
#include <math.h>
#include <stdint.h>

// Problem constants
#define BB   2
#define SS   2048
#define DD   768
#define HH   12
#define HDIM 64
#define QKVD 2304           // 3*D per token
#define NTOK (BB*SS)        // 4096

// Scratch (allocation-free rule: __device__ globals)
__device__ float g_qkv[(size_t)NTOK * QKVD];   // [4096, 2304] row-major fp32
__device__ float g_attn[(size_t)NTOK * DD];    // attn out, row-major fp32
__device__ float g_attnA[(size_t)NTOK * DD];   // attn out as A-image (tf32)
__device__ float g_rope[(size_t)NTOK * 64];    // [token][cos32|sin32]
__device__ float g_hidA[(size_t)NTOK * DD];    // hidden as A-image (tf32)
__device__ float g_wqB[(size_t)QKVD * DD];     // Wqkv as B-image (tf32)
__device__ float g_woB[(size_t)DD * DD];       // Wo as B-image (tf32)

__device__ __forceinline__ float to_tf32(float x) {
    uint32_t u;
    asm("cvt.rna.tf32.f32 %0, %1;" : "=r"(u) : "f"(x));
    return __uint_as_float(u);
}

__device__ __forceinline__ uint32_t smem_u32(const void* p) {
    uint32_t a;
    asm("{ .reg .u64 t; cvta.to.shared.u64 t, %1; cvt.u32.u64 %0, t; }"
        : "=r"(a) : "l"(p));
    return a;
}

__device__ __forceinline__ void mma_tf32(float c[4], const uint32_t a[4], const uint32_t b[2]) {
    asm volatile(
        "mma.sync.aligned.m16n8k8.row.col.f32.tf32.tf32.f32 "
        "{%0,%1,%2,%3}, {%4,%5,%6,%7}, {%8,%9}, {%0,%1,%2,%3};"
        : "+f"(c[0]), "+f"(c[1]), "+f"(c[2]), "+f"(c[3])
        : "r"(a[0]), "r"(a[1]), "r"(a[2]), "r"(a[3]), "r"(b[0]), "r"(b[1]));
}

#define CP_ASYNC16(dst, src) \
    asm volatile("cp.async.cg.shared.global [%0], [%1], 16;" :: "r"(dst), "l"(src))
#define CP_COMMIT() asm volatile("cp.async.commit_group;" ::: "memory")
#define CP_WAIT2()  asm volatile("cp.async.wait_group 2;"  ::: "memory")

// ---------------------------------------------------------------------------
// Tile-image layouts (tf32). Tile: 128 rows x 32 k-cols = 4096 floats.
// ---------------------------------------------------------------------------
__device__ __forceinline__ size_t aimg_off(int r, int k, int ntileK) {
    const int mt = r >> 7, kc = k >> 5;
    const int mi = (r >> 4) & 7, rr = r & 15;
    const int ki = (k >> 3) & 3, c = k & 7;
    const int lane = ((rr & 7) << 2) + (c & 3);
    const int e = (rr >> 3) + ((c >> 2) << 1);
    return ((size_t)(mt * ntileK + kc) << 12) + (((mi << 2) + ki) << 7) + (lane << 2) + e;
}
__device__ __forceinline__ size_t bimg_off(int n, int k, int ntileK) {
    const int nt = n >> 7, kc = k >> 5;
    const int pr = (n >> 4) & 7, p = (n >> 3) & 1, nn = n & 7;
    const int ki = (k >> 3) & 3;
    const int lane = (nn << 2) + (k & 3);
    const int e = (p << 1) + ((k & 7) >> 2);
    return ((size_t)(nt * ntileK + kc) << 12) + (((pr << 2) + ki) << 7) + (lane << 2) + e;
}

__global__ void xform_a(const float* __restrict__ X, float* __restrict__ img, int R, int K)
{
    const int idx = blockIdx.x * 256 + threadIdx.x;
    const int kq = K >> 2;
    if (idx >= R * kq) return;
    const int r = idx / kq, k = (idx - r * kq) << 2;
    const float4 v = *(const float4*)(X + (size_t)r * K + k);
    const int ntileK = K >> 5;
    img[aimg_off(r, k + 0, ntileK)] = to_tf32(v.x);
    img[aimg_off(r, k + 1, ntileK)] = to_tf32(v.y);
    img[aimg_off(r, k + 2, ntileK)] = to_tf32(v.z);
    img[aimg_off(r, k + 3, ntileK)] = to_tf32(v.w);
}

__global__ void xform_b(const float* __restrict__ X, float* __restrict__ img, int R, int K)
{
    const int idx = blockIdx.x * 256 + threadIdx.x;
    const int kq = K >> 2;
    if (idx >= R * kq) return;
    const int n = idx / kq, k = (idx - n * kq) << 2;
    const float4 v = *(const float4*)(X + (size_t)n * K + k);
    const int ntileK = K >> 5;
    img[bimg_off(n, k + 0, ntileK)] = to_tf32(v.x);
    img[bimg_off(n, k + 1, ntileK)] = to_tf32(v.y);
    img[bimg_off(n, k + 2, ntileK)] = to_tf32(v.z);
    img[bimg_off(n, k + 3, ntileK)] = to_tf32(v.w);
}

// ---------------------------------------------------------------------------
// RoPE table
// ---------------------------------------------------------------------------
__global__ void rope_table(const int* __restrict__ pos_ids)
{
    const int idx = blockIdx.x * 256 + threadIdx.x;
    if (idx >= NTOK * 32) return;
    const int bs = idx >> 5;
    const int d  = idx & 31;
    const float FCOEF = -0.41524101186091903f;
    const float pos = (float)pos_ids[bs];
    const float f = pos * exp2f((float)d * FCOEF);
    float sn, cs;
    sincosf(f, &sn, &cs);
    g_rope[(size_t)bs * 64 + d]      = cs;
    g_rope[(size_t)bs * 64 + 32 + d] = sn;
}

// ---------------------------------------------------------------------------
// GEMM on tile images: C[M,N] = A * B^T. CTA 128x128x32, 4 warps (2m x 2n),
// warp tile 64x64. cp.async 3-stage. 2 CTAs/SM. grid = (N/128, M/128).
// ---------------------------------------------------------------------------
#define GEMM_SMEM 98304   // 3 stages x (16KB A + 16KB B)

__global__ __launch_bounds__(128, 2) void gemm_img(const float* __restrict__ Aimg,
                                                   const float* __restrict__ Bimg,
                                                   float* __restrict__ C,
                                                   int N, int ntileK)
{
    extern __shared__ float smf[];
    const uint32_t sbase = smem_u32(smf);
    const int tid    = threadIdx.x;
    const int wid    = tid >> 5;
    const int lane   = tid & 31;
    const int mt     = blockIdx.y;
    const int nt     = blockIdx.x;
    const int warp_m = wid >> 1;   // 0..1
    const int warp_n = wid & 1;    // 0..1

    float acc[4][8][4];
#pragma unroll
    for (int a = 0; a < 4; a++)
#pragma unroll
        for (int b = 0; b < 8; b++)
#pragma unroll
            for (int r = 0; r < 4; r++) acc[a][b][r] = 0.f;

    const int nch = ntileK;

    const float* Atile0 = Aimg + ((size_t)(mt * ntileK) << 12) + (tid << 2);
    const float* Btile0 = Bimg + ((size_t)(nt * ntileK) << 12) + (tid << 2);

#define ISSUE(c) do {                                                     \
    if ((c) < nch) {                                                      \
        const float* As_ = Atile0 + ((size_t)(c) << 12);                  \
        const float* Bs_ = Btile0 + ((size_t)(c) << 12);                  \
        uint32_t sa_ = sbase + ((c) % 3) * 32768u + (tid << 4);           \
        uint32_t sb_ = sa_ + 16384u;                                      \
        _Pragma("unroll")                                                 \
        for (int i_ = 0; i_ < 8; i_++) {                                  \
            CP_ASYNC16(sa_ + i_ * 2048u, As_ + i_ * 512);                 \
            CP_ASYNC16(sb_ + i_ * 2048u, Bs_ + i_ * 512);                 \
        }                                                                 \
    }                                                                     \
    CP_COMMIT();                                                          \
} while (0)

    ISSUE(0); ISSUE(1); ISSUE(2);

    const int afo = warp_m * 2048 + lane * 4;          // +512 per a, +128 per ki
    const int bfo = 4096 + warp_n * 2048 + lane * 4;   // +512 per t, +128 per ki

    for (int c = 0; c < nch; c++) {
        CP_WAIT2();
        __syncthreads();

        const float* s = smf + (c % 3) * 8192;
#pragma unroll
        for (int ki = 0; ki < 4; ki++) {
            uint32_t af[4][4], bf[8][2];
#pragma unroll
            for (int a = 0; a < 4; a++) {
                float4 v = *(const float4*)(s + afo + a * 512 + ki * 128);
                af[a][0] = __float_as_uint(v.x); af[a][1] = __float_as_uint(v.y);
                af[a][2] = __float_as_uint(v.z); af[a][3] = __float_as_uint(v.w);
            }
#pragma unroll
            for (int t = 0; t < 4; t++) {
                float4 v = *(const float4*)(s + bfo + t * 512 + ki * 128);
                bf[2*t][0]   = __float_as_uint(v.x); bf[2*t][1]   = __float_as_uint(v.y);
                bf[2*t+1][0] = __float_as_uint(v.z); bf[2*t+1][1] = __float_as_uint(v.w);
            }
#pragma unroll
            for (int a = 0; a < 4; a++)
#pragma unroll
                for (int b = 0; b < 8; b++)
                    mma_tf32(acc[a][b], af[a], bf[b]);
        }
        __syncthreads();
        ISSUE(c + 3);
    }

    // epilogue: row-major fp32 C
    const int g = lane >> 2, u = lane & 3;
#pragma unroll
    for (int a = 0; a < 4; a++) {
        const int row = mt * 128 + warp_m * 64 + a * 16 + g;
#pragma unroll
        for (int b = 0; b < 8; b++) {
            const int col = nt * 128 + warp_n * 64 + b * 8 + 2 * u;
            *(float2*)(C + (size_t)row * N + col)       = make_float2(acc[a][b][0], acc[a][b][1]);
            *(float2*)(C + (size_t)(row + 8) * N + col) = make_float2(acc[a][b][2], acc[a][b][3]);
        }
    }
#undef ISSUE
}

// ---------------------------------------------------------------------------
// Fused RoPE (table) + sliding-window attention on mma.sync tf32.
// Output row-major fp32 (coalesced), re-imaged by xform_a afterwards.
// ---------------------------------------------------------------------------
#define KPITCH 68
#define VPITCH 72
#define QPITCH 68
#define KOFF 0
#define VOFF (256 * KPITCH)
#define QOFF (VOFF + 256 * VPITCH)
#define ATTN_SMEM ((QOFF + 128 * QPITCH) * 4)

__device__ __forceinline__ float4 tf32_4(float4 v) {
    v.x = to_tf32(v.x); v.y = to_tf32(v.y); v.z = to_tf32(v.z); v.w = to_tf32(v.w);
    return v;
}

__device__ __forceinline__ void rope4t(float4 cs, float4 sn, float4 x, float4 y,
                                       float4& lo, float4& hi)
{
    lo.x = x.x * cs.x - y.x * sn.x;  hi.x = y.x * cs.x + x.x * sn.x;
    lo.y = x.y * cs.y - y.y * sn.y;  hi.y = y.y * cs.y + x.y * sn.y;
    lo.z = x.z * cs.z - y.z * sn.z;  hi.z = y.z * cs.z + x.z * sn.z;
    lo.w = x.w * cs.w - y.w * sn.w;  hi.w = y.w * cs.w + x.w * sn.w;
}

__global__ __launch_bounds__(256) void attn_mma()
{
    extern __shared__ float sm[];
    float* Ks = sm + KOFF;
    float* Vs = sm + VOFF;
    float* Qs = sm + QOFF;

    const int tid  = threadIdx.x;
    const int lane = tid & 31;
    const int w    = tid >> 5;
    const int qb   = blockIdx.x;
    const int bh   = blockIdx.y;
    const int b    = bh / HH;
    const int h    = bh % HH;
    const int kstart = qb * 128 - 64;

    {
        const int r  = tid;
        const int kg = kstart + r;
        float* kd = Ks + r * KPITCH;
        float* vd = Vs + r * VPITCH;
        if (kg >= 0 && kg < SS) {
            const float* kp = g_qkv + ((size_t)(b * SS + kg)) * QKVD + DD + h * HDIM;
            const float* vp = kp + DD;
            const float* rp = g_rope + ((size_t)(b * SS + kg)) * 64;
#pragma unroll
            for (int i = 0; i < 8; i++) {
                float4 x  = ((const float4*)kp)[i];
                float4 y  = ((const float4*)kp)[i + 8];
                float4 cs = ((const float4*)rp)[i];
                float4 sn = ((const float4*)rp)[i + 8];
                float4 lo, hi;
                rope4t(cs, sn, x, y, lo, hi);
                ((float4*)kd)[i]     = tf32_4(lo);
                ((float4*)kd)[i + 8] = tf32_4(hi);
            }
#pragma unroll
            for (int i = 0; i < 16; i++)
                ((float4*)vd)[i] = tf32_4(((const float4*)vp)[i]);
        } else {
#pragma unroll
            for (int i = 0; i < 16; i++)
                ((float4*)vd)[i] = make_float4(0.f, 0.f, 0.f, 0.f);
        }
        if (tid < 128) {
            const int qg = qb * 128 + tid;
            const float* qp = g_qkv + ((size_t)(b * SS + qg)) * QKVD + h * HDIM;
            const float* rp = g_rope + ((size_t)(b * SS + qg)) * 64;
            float* qd = Qs + tid * QPITCH;
            const float QSC = 0.125f * 1.4426950408889634f;
#pragma unroll
            for (int i = 0; i < 8; i++) {
                float4 x  = ((const float4*)qp)[i];
                float4 y  = ((const float4*)qp)[i + 8];
                float4 cs = ((const float4*)rp)[i];
                float4 sn = ((const float4*)rp)[i + 8];
                float4 lo, hi;
                rope4t(cs, sn, x, y, lo, hi);
                lo.x *= QSC; lo.y *= QSC; lo.z *= QSC; lo.w *= QSC;
                hi.x *= QSC; hi.y *= QSC; hi.z *= QSC; hi.w *= QSC;
                ((float4*)qd)[i]     = tf32_4(lo);
                ((float4*)qd)[i + 8] = tf32_4(hi);
            }
        }
    }
    __syncthreads();

    const int rl = (w << 4) + (lane >> 2);
    const int cq = lane & 3;
    uint32_t aq[8][4];
#pragma unroll
    for (int s = 0; s < 8; s++) {
        aq[s][0] = __float_as_uint(Qs[rl * QPITCH + cq + 8 * s]);
        aq[s][1] = __float_as_uint(Qs[(rl + 8) * QPITCH + cq + 8 * s]);
        aq[s][2] = __float_as_uint(Qs[rl * QPITCH + cq + 8 * s + 4]);
        aq[s][3] = __float_as_uint(Qs[(rl + 8) * QPITCH + cq + 8 * s + 4]);
    }
    __syncwarp();

    float m0 = -1e4f, m1 = -1e4f, l0 = 0.f, l1 = 0.f;
    float oacc[8][4];
#pragma unroll
    for (int d = 0; d < 8; d++)
#pragma unroll
        for (int r = 0; r < 4; r++) oacc[d][r] = 0.f;

    float* Pw = Qs + (w << 4) * QPITCH;
    const int cw = (w >= 4) ? 1 : 0;

    for (int ci = 0; ci < 3; ci++) {
        const int kbase = (cw + ci) * 64;

        float sacc[8][4];
#pragma unroll
        for (int j = 0; j < 8; j++)
#pragma unroll
            for (int r = 0; r < 4; r++) sacc[j][r] = 0.f;

        const float* kb[8];
#pragma unroll
        for (int jt = 0; jt < 8; jt++)
            kb[jt] = Ks + (kbase + 8 * jt + (lane >> 2)) * KPITCH + (lane & 3);

#pragma unroll
        for (int s = 0; s < 8; s++) {
#pragma unroll
            for (int jt = 0; jt < 8; jt++) {
                uint32_t bk[2];
                bk[0] = __float_as_uint(kb[jt][8 * s]);
                bk[1] = __float_as_uint(kb[jt][8 * s + 4]);
                mma_tf32(sacc[jt], aq[s], bk);
            }
        }

        float mx0 = -30000.f, mx1 = -30000.f;
#pragma unroll
        for (int jt = 0; jt < 8; jt++) {
            const int k0 = kbase + 8 * jt + 2 * (lane & 3);
            const int k1 = k0 + 1;
            const int kg0 = kstart + k0, kg1 = kstart + k1;
            const bool in0 = (kg0 >= 0) & (kg0 < SS);
            const bool in1 = (kg1 >= 0) & (kg1 < SS);
            const bool v00 = in0 && ((unsigned)(k0 - rl) <= 128u);
            const bool v01 = in1 && ((unsigned)(k1 - rl) <= 128u);
            const bool v10 = in0 && ((unsigned)(k0 - rl - 8) <= 128u);
            const bool v11 = in1 && ((unsigned)(k1 - rl - 8) <= 128u);
            sacc[jt][0] = v00 ? sacc[jt][0] : -30000.f;
            sacc[jt][1] = v01 ? sacc[jt][1] : -30000.f;
            sacc[jt][2] = v10 ? sacc[jt][2] : -30000.f;
            sacc[jt][3] = v11 ? sacc[jt][3] : -30000.f;
            mx0 = fmaxf(mx0, fmaxf(sacc[jt][0], sacc[jt][1]));
            mx1 = fmaxf(mx1, fmaxf(sacc[jt][2], sacc[jt][3]));
        }
        mx0 = fmaxf(mx0, __shfl_xor_sync(0xffffffff, mx0, 1));
        mx0 = fmaxf(mx0, __shfl_xor_sync(0xffffffff, mx0, 2));
        mx1 = fmaxf(mx1, __shfl_xor_sync(0xffffffff, mx1, 1));
        mx1 = fmaxf(mx1, __shfl_xor_sync(0xffffffff, mx1, 2));

        const float m0n = fmaxf(m0, mx0);
        const float m1n = fmaxf(m1, mx1);
        const float a0 = exp2f(m0 - m0n);
        const float a1 = exp2f(m1 - m1n);
        m0 = m0n; m1 = m1n;
        l0 *= a0; l1 *= a1;
#pragma unroll
        for (int d = 0; d < 8; d++) {
            oacc[d][0] *= a0; oacc[d][1] *= a0;
            oacc[d][2] *= a1; oacc[d][3] *= a1;
        }

        float rs0 = 0.f, rs1 = 0.f;
        const int prow = (lane >> 2);
#pragma unroll
        for (int jt = 0; jt < 8; jt++) {
            float p00 = to_tf32(exp2f(sacc[jt][0] - m0));
            float p01 = to_tf32(exp2f(sacc[jt][1] - m0));
            float p10 = to_tf32(exp2f(sacc[jt][2] - m1));
            float p11 = to_tf32(exp2f(sacc[jt][3] - m1));
            rs0 += p00 + p01;
            rs1 += p10 + p11;
            const int pc = 8 * jt + 2 * (lane & 3);
            *(float2*)(Pw + prow * QPITCH + pc)       = make_float2(p00, p01);
            *(float2*)(Pw + (prow + 8) * QPITCH + pc) = make_float2(p10, p11);
        }
        rs0 += __shfl_xor_sync(0xffffffff, rs0, 1);
        rs0 += __shfl_xor_sync(0xffffffff, rs0, 2);
        rs1 += __shfl_xor_sync(0xffffffff, rs1, 1);
        rs1 += __shfl_xor_sync(0xffffffff, rs1, 2);
        l0 += rs0; l1 += rs1;
        __syncwarp();

#pragma unroll
        for (int s = 0; s < 8; s++) {
            uint32_t pa[4];
            const float* pb = Pw + prow * QPITCH + (lane & 3) + 8 * s;
            pa[0] = __float_as_uint(pb[0]);
            pa[1] = __float_as_uint(pb[8 * QPITCH]);
            pa[2] = __float_as_uint(pb[4]);
            pa[3] = __float_as_uint(pb[8 * QPITCH + 4]);
            const float* vb = Vs + (kbase + 8 * s + (lane & 3)) * VPITCH + (lane >> 2);
#pragma unroll
            for (int dt = 0; dt < 8; dt++) {
                uint32_t bv[2];
                bv[0] = __float_as_uint(vb[8 * dt]);
                bv[1] = __float_as_uint(vb[4 * VPITCH + 8 * dt]);
                mma_tf32(oacc[dt], pa, bv);
            }
        }
        __syncwarp();
    }

    // ---- normalize + coalesced row-major write ----
    const float inv0 = 1.f / l0;
    const float inv1 = 1.f / l1;
    const int rg = qb * 128 + rl;
    float* og0 = g_attn + ((size_t)(b * SS + rg)) * DD + h * HDIM;
    float* og1 = og0 + 8 * DD;
#pragma unroll
    for (int dt = 0; dt < 8; dt++) {
        const int col = 8 * dt + 2 * (lane & 3);
        *(float2*)(og0 + col) = make_float2(oacc[dt][0] * inv0, oacc[dt][1] * inv0);
        *(float2*)(og1 + col) = make_float2(oacc[dt][2] * inv1, oacc[dt][3] * inv1);
    }
}

// ---------------------------------------------------------------------------
extern "C" void kernel_launch(void* const* d_in, const int* in_sizes, int n_in,
                              void* d_out, int out_size)
{
    const float* hidden = (const float*)d_in[0];
    const float* wqkv   = (const float*)d_in[1];
    const float* wo     = (const float*)d_in[2];
    const int*   pos    = (const int*)d_in[4];
    float*       out    = (float*)d_out;

    float *qkv_p, *attn_p, *attnA_p, *hidA_p, *wqB_p, *woB_p;
    cudaGetSymbolAddress((void**)&qkv_p,   g_qkv);
    cudaGetSymbolAddress((void**)&attn_p,  g_attn);
    cudaGetSymbolAddress((void**)&attnA_p, g_attnA);
    cudaGetSymbolAddress((void**)&hidA_p,  g_hidA);
    cudaGetSymbolAddress((void**)&wqB_p,   g_wqB);
    cudaGetSymbolAddress((void**)&woB_p,   g_woB);

    cudaFuncSetAttribute(gemm_img, cudaFuncAttributeMaxDynamicSharedMemorySize, GEMM_SMEM);
    cudaFuncSetAttribute(attn_mma, cudaFuncAttributeMaxDynamicSharedMemorySize, ATTN_SMEM);

    // 0) RoPE table + operand transforms (tf32 tile images)
    rope_table<<<(NTOK * 32 + 255) / 256, 256>>>(pos);
    xform_a<<<(NTOK * DD / 4 + 255) / 256, 256>>>(hidden, hidA_p, NTOK, DD);
    xform_b<<<(QKVD * DD / 4 + 255) / 256, 256>>>(wqkv, wqB_p, QKVD, DD);
    xform_b<<<(DD * DD / 4 + 255) / 256, 256>>>(wo, woB_p, DD, DD);

    // 1) QKV = hidden @ Wqkv^T   [4096, 2304] row-major fp32
    gemm_img<<<dim3(QKVD / 128, NTOK / 128), 128, GEMM_SMEM>>>(hidA_p, wqB_p, qkv_p,
                                                               QKVD, DD / 32);
    // 2) fused RoPE + sliding-window attention -> g_attn (row-major fp32)
    attn_mma<<<dim3(SS / 128, BB * HH), 256, ATTN_SMEM>>>();
    // 2b) re-image attn output for Wo GEMM
    xform_a<<<(NTOK * DD / 4 + 255) / 256, 256>>>(attn_p, attnA_p, NTOK, DD);
    // 3) out = attn @ Wo^T       [4096, 768] row-major fp32
    gemm_img<<<dim3(DD / 128, NTOK / 128), 128, GEMM_SMEM>>>(attnA_p, woB_p, out,
                                                             DD, DD / 32);
}

// round 8
// speedup vs baseline: 1.3778x; 1.3778x over previous
#include <cuda_runtime.h>
#include <cuda_fp16.h>
#include <math.h>
#include <stdint.h>

// Problem constants
#define BB   2
#define SS   2048
#define DD   768
#define HH   12
#define HDIM 64
#define QKVD 2304           // 3*D per token
#define NTOK (BB*SS)        // 4096

// Scratch (allocation-free rule: __device__ globals)
__device__ float  g_qkv[(size_t)NTOK * QKVD];   // [4096, 2304] row-major fp32
__device__ float  g_attn[(size_t)NTOK * DD];    // attn out, row-major fp32
__device__ float  g_rope[(size_t)NTOK * 64];    // [token][cos32|sin32]
__device__ __half g_hidH[(size_t)NTOK * DD];    // hidden as A-image (fp16)
__device__ __half g_attnH[(size_t)NTOK * DD];   // attn out as A-image (fp16)
__device__ __half g_wqH[(size_t)QKVD * DD];     // Wqkv as B-image (fp16)
__device__ __half g_woH[(size_t)DD * DD];       // Wo as B-image (fp16)

__device__ __forceinline__ float to_tf32(float x) {
    uint32_t u;
    asm("cvt.rna.tf32.f32 %0, %1;" : "=r"(u) : "f"(x));
    return __uint_as_float(u);
}

__device__ __forceinline__ uint32_t smem_u32(const void* p) {
    uint32_t a;
    asm("{ .reg .u64 t; cvta.to.shared.u64 t, %1; cvt.u32.u64 %0, t; }"
        : "=r"(a) : "l"(p));
    return a;
}

__device__ __forceinline__ void mma_tf32(float c[4], const uint32_t a[4], const uint32_t b[2]) {
    asm volatile(
        "mma.sync.aligned.m16n8k8.row.col.f32.tf32.tf32.f32 "
        "{%0,%1,%2,%3}, {%4,%5,%6,%7}, {%8,%9}, {%0,%1,%2,%3};"
        : "+f"(c[0]), "+f"(c[1]), "+f"(c[2]), "+f"(c[3])
        : "r"(a[0]), "r"(a[1]), "r"(a[2]), "r"(a[3]), "r"(b[0]), "r"(b[1]));
}

__device__ __forceinline__ void mma_f16(float c[4], const uint32_t a[4], const uint32_t b[2]) {
    asm volatile(
        "mma.sync.aligned.m16n8k16.row.col.f32.f16.f16.f32 "
        "{%0,%1,%2,%3}, {%4,%5,%6,%7}, {%8,%9}, {%0,%1,%2,%3};"
        : "+f"(c[0]), "+f"(c[1]), "+f"(c[2]), "+f"(c[3])
        : "r"(a[0]), "r"(a[1]), "r"(a[2]), "r"(a[3]), "r"(b[0]), "r"(b[1]));
}

#define CP_ASYNC16(dst, src) \
    asm volatile("cp.async.cg.shared.global [%0], [%1], 16;" :: "r"(dst), "l"(src))
#define CP_COMMIT() asm volatile("cp.async.commit_group;" ::: "memory")
#define CP_WAIT3()  asm volatile("cp.async.wait_group 3;"  ::: "memory")

// ---------------------------------------------------------------------------
// fp16 tile-image layouts. Tile: 128 rows x 32 k-cols = 4096 halves (8 KB).
// A subtile m16k16 = 512B: lane=(rr&7)*4+((kk&7)>>1), e=(kk&1)+2*(rr>>3)+4*(kk>>3)
// B pair-block n16k16 = 512B: lane=nn*4+((kk&7)>>1), e=(kk&1)+2*(kk>>3)+4*p
// ---------------------------------------------------------------------------
__device__ __forceinline__ size_t aimg_off_h(int r, int k, int ntileK) {
    const int mt = r >> 7, kc = k >> 5;
    const int mi = (r >> 4) & 7, rr = r & 15;
    const int ki = (k >> 4) & 1, kk = k & 15;
    const int lane = ((rr & 7) << 2) + ((kk & 7) >> 1);
    const int e = (kk & 1) + ((rr >> 3) << 1) + ((kk >> 3) << 2);
    return ((size_t)(mt * ntileK + kc) << 12) + (((mi << 1) + ki) << 8) + (lane << 3) + e;
}
__device__ __forceinline__ size_t bimg_off_h(int n, int k, int ntileK) {
    const int nt = n >> 7, kc = k >> 5;
    const int pr = (n >> 4) & 7, p = (n >> 3) & 1, nn = n & 7;
    const int ki = (k >> 4) & 1, kk = k & 15;
    const int lane = (nn << 2) + ((kk & 7) >> 1);
    const int e = (kk & 1) + ((kk >> 3) << 1) + (p << 2);
    return ((size_t)(nt * ntileK + kc) << 12) + (((pr << 1) + ki) << 8) + (lane << 3) + e;
}

// k is 4-aligned; (k,k+1) and (k+2,k+3) land as half2 pairs at even e.
__global__ void xform_a_h(const float* __restrict__ X, __half* __restrict__ img, int R, int K)
{
    const int idx = blockIdx.x * 256 + threadIdx.x;
    const int kq = K >> 2;
    if (idx >= R * kq) return;
    const int r = idx / kq, k = (idx - r * kq) << 2;
    const float4 v = *(const float4*)(X + (size_t)r * K + k);
    const int ntileK = K >> 5;
    *(__half2*)(img + aimg_off_h(r, k,     ntileK)) = __floats2half2_rn(v.x, v.y);
    *(__half2*)(img + aimg_off_h(r, k + 2, ntileK)) = __floats2half2_rn(v.z, v.w);
}

__global__ void xform_b_h(const float* __restrict__ X, __half* __restrict__ img, int R, int K)
{
    const int idx = blockIdx.x * 256 + threadIdx.x;
    const int kq = K >> 2;
    if (idx >= R * kq) return;
    const int n = idx / kq, k = (idx - n * kq) << 2;
    const float4 v = *(const float4*)(X + (size_t)n * K + k);
    const int ntileK = K >> 5;
    *(__half2*)(img + bimg_off_h(n, k,     ntileK)) = __floats2half2_rn(v.x, v.y);
    *(__half2*)(img + bimg_off_h(n, k + 2, ntileK)) = __floats2half2_rn(v.z, v.w);
}

// ---------------------------------------------------------------------------
// RoPE table
// ---------------------------------------------------------------------------
__global__ void rope_table(const int* __restrict__ pos_ids)
{
    const int idx = blockIdx.x * 256 + threadIdx.x;
    if (idx >= NTOK * 32) return;
    const int bs = idx >> 5;
    const int d  = idx & 31;
    const float FCOEF = -0.41524101186091903f;
    const float pos = (float)pos_ids[bs];
    const float f = pos * exp2f((float)d * FCOEF);
    float sn, cs;
    sincosf(f, &sn, &cs);
    g_rope[(size_t)bs * 64 + d]      = cs;
    g_rope[(size_t)bs * 64 + 32 + d] = sn;
}

// ---------------------------------------------------------------------------
// fp16 GEMM on tile images: C[M,N] = A * B^T (fp32 out).
// CTA 128x128x32, 8 warps (2m x 4n), warp tile 64x32, m16n8k16.
// 4-stage cp.async pipeline (16KB/stage), 2 CTAs/SM. grid (N/128, M/128).
// ---------------------------------------------------------------------------
#define GEMM_SMEM 65536   // 4 stages x (8KB A + 8KB B)

__global__ __launch_bounds__(256, 2) void gemm_h(const __half* __restrict__ Aimg,
                                                 const __half* __restrict__ Bimg,
                                                 float* __restrict__ C,
                                                 int N, int ntileK)
{
    extern __shared__ __half smh[];
    const uint32_t sbase = smem_u32(smh);
    const int tid    = threadIdx.x;
    const int wid    = tid >> 5;
    const int lane   = tid & 31;
    const int mt     = blockIdx.y;
    const int nt     = blockIdx.x;
    const int warp_m = wid >> 2;   // 0..1
    const int warp_n = wid & 3;    // 0..3

    float acc[4][4][4];
#pragma unroll
    for (int a = 0; a < 4; a++)
#pragma unroll
        for (int b = 0; b < 4; b++)
#pragma unroll
            for (int r = 0; r < 4; r++) acc[a][b][r] = 0.f;

    const int nch = ntileK;
    const __half* Atile0 = Aimg + ((size_t)(mt * ntileK) << 12) + (tid << 3);
    const __half* Btile0 = Bimg + ((size_t)(nt * ntileK) << 12) + (tid << 3);

#define ISSUE(c) do {                                                     \
    if ((c) < nch) {                                                      \
        const __half* As_ = Atile0 + ((size_t)(c) << 12);                 \
        const __half* Bs_ = Btile0 + ((size_t)(c) << 12);                 \
        uint32_t sa_ = sbase + ((c) & 3) * 16384u + (tid << 4);           \
        CP_ASYNC16(sa_,          As_);                                    \
        CP_ASYNC16(sa_ + 4096u,  As_ + 2048);                             \
        CP_ASYNC16(sa_ + 8192u,  Bs_);                                    \
        CP_ASYNC16(sa_ + 12288u, Bs_ + 2048);                             \
    }                                                                     \
    CP_COMMIT();                                                          \
} while (0)

    ISSUE(0); ISSUE(1); ISSUE(2); ISSUE(3);

    const int afo = warp_m * 2048 + lane * 8;          // halves; +512/a, +256/ki
    const int bfo = 4096 + warp_n * 1024 + lane * 8;   // halves; +512/t, +256/ki

    for (int c = 0; c < nch; c++) {
        CP_WAIT3();
        __syncthreads();

        const __half* s = smh + (c & 3) * 8192;        // 8192 halves per stage
#pragma unroll
        for (int ki = 0; ki < 2; ki++) {
            uint32_t af[4][4], bf[4][2];
#pragma unroll
            for (int a = 0; a < 4; a++) {
                uint4 v = *(const uint4*)(s + afo + a * 512 + ki * 256);
                af[a][0] = v.x; af[a][1] = v.y; af[a][2] = v.z; af[a][3] = v.w;
            }
#pragma unroll
            for (int t = 0; t < 2; t++) {
                uint4 v = *(const uint4*)(s + bfo + t * 512 + ki * 256);
                bf[2*t][0]   = v.x; bf[2*t][1]   = v.y;
                bf[2*t+1][0] = v.z; bf[2*t+1][1] = v.w;
            }
#pragma unroll
            for (int a = 0; a < 4; a++)
#pragma unroll
                for (int b = 0; b < 4; b++)
                    mma_f16(acc[a][b], af[a], bf[b]);
        }
        __syncthreads();
        ISSUE(c + 4);
    }

    const int g = lane >> 2, u = lane & 3;
#pragma unroll
    for (int a = 0; a < 4; a++) {
        const int row = mt * 128 + warp_m * 64 + a * 16 + g;
#pragma unroll
        for (int b = 0; b < 4; b++) {
            const int col = nt * 128 + warp_n * 32 + b * 8 + 2 * u;
            *(float2*)(C + (size_t)row * N + col)       = make_float2(acc[a][b][0], acc[a][b][1]);
            *(float2*)(C + (size_t)(row + 8) * N + col) = make_float2(acc[a][b][2], acc[a][b][3]);
        }
    }
#undef ISSUE
}

// ---------------------------------------------------------------------------
// Fused RoPE (table) + sliding-window attention on mma.sync tf32 (unchanged).
// ---------------------------------------------------------------------------
#define KPITCH 68
#define VPITCH 72
#define QPITCH 68
#define KOFF 0
#define VOFF (256 * KPITCH)
#define QOFF (VOFF + 256 * VPITCH)
#define ATTN_SMEM ((QOFF + 128 * QPITCH) * 4)

__device__ __forceinline__ float4 tf32_4(float4 v) {
    v.x = to_tf32(v.x); v.y = to_tf32(v.y); v.z = to_tf32(v.z); v.w = to_tf32(v.w);
    return v;
}

__device__ __forceinline__ void rope4t(float4 cs, float4 sn, float4 x, float4 y,
                                       float4& lo, float4& hi)
{
    lo.x = x.x * cs.x - y.x * sn.x;  hi.x = y.x * cs.x + x.x * sn.x;
    lo.y = x.y * cs.y - y.y * sn.y;  hi.y = y.y * cs.y + x.y * sn.y;
    lo.z = x.z * cs.z - y.z * sn.z;  hi.z = y.z * cs.z + x.z * sn.z;
    lo.w = x.w * cs.w - y.w * sn.w;  hi.w = y.w * cs.w + x.w * sn.w;
}

__global__ __launch_bounds__(256) void attn_mma()
{
    extern __shared__ float sm[];
    float* Ks = sm + KOFF;
    float* Vs = sm + VOFF;
    float* Qs = sm + QOFF;

    const int tid  = threadIdx.x;
    const int lane = tid & 31;
    const int w    = tid >> 5;
    const int qb   = blockIdx.x;
    const int bh   = blockIdx.y;
    const int b    = bh / HH;
    const int h    = bh % HH;
    const int kstart = qb * 128 - 64;

    {
        const int r  = tid;
        const int kg = kstart + r;
        float* kd = Ks + r * KPITCH;
        float* vd = Vs + r * VPITCH;
        if (kg >= 0 && kg < SS) {
            const float* kp = g_qkv + ((size_t)(b * SS + kg)) * QKVD + DD + h * HDIM;
            const float* vp = kp + DD;
            const float* rp = g_rope + ((size_t)(b * SS + kg)) * 64;
#pragma unroll
            for (int i = 0; i < 8; i++) {
                float4 x  = ((const float4*)kp)[i];
                float4 y  = ((const float4*)kp)[i + 8];
                float4 cs = ((const float4*)rp)[i];
                float4 sn = ((const float4*)rp)[i + 8];
                float4 lo, hi;
                rope4t(cs, sn, x, y, lo, hi);
                ((float4*)kd)[i]     = tf32_4(lo);
                ((float4*)kd)[i + 8] = tf32_4(hi);
            }
#pragma unroll
            for (int i = 0; i < 16; i++)
                ((float4*)vd)[i] = tf32_4(((const float4*)vp)[i]);
        } else {
#pragma unroll
            for (int i = 0; i < 16; i++)
                ((float4*)vd)[i] = make_float4(0.f, 0.f, 0.f, 0.f);
        }
        if (tid < 128) {
            const int qg = qb * 128 + tid;
            const float* qp = g_qkv + ((size_t)(b * SS + qg)) * QKVD + h * HDIM;
            const float* rp = g_rope + ((size_t)(b * SS + qg)) * 64;
            float* qd = Qs + tid * QPITCH;
            const float QSC = 0.125f * 1.4426950408889634f;
#pragma unroll
            for (int i = 0; i < 8; i++) {
                float4 x  = ((const float4*)qp)[i];
                float4 y  = ((const float4*)qp)[i + 8];
                float4 cs = ((const float4*)rp)[i];
                float4 sn = ((const float4*)rp)[i + 8];
                float4 lo, hi;
                rope4t(cs, sn, x, y, lo, hi);
                lo.x *= QSC; lo.y *= QSC; lo.z *= QSC; lo.w *= QSC;
                hi.x *= QSC; hi.y *= QSC; hi.z *= QSC; hi.w *= QSC;
                ((float4*)qd)[i]     = tf32_4(lo);
                ((float4*)qd)[i + 8] = tf32_4(hi);
            }
        }
    }
    __syncthreads();

    const int rl = (w << 4) + (lane >> 2);
    const int cq = lane & 3;
    uint32_t aq[8][4];
#pragma unroll
    for (int s = 0; s < 8; s++) {
        aq[s][0] = __float_as_uint(Qs[rl * QPITCH + cq + 8 * s]);
        aq[s][1] = __float_as_uint(Qs[(rl + 8) * QPITCH + cq + 8 * s]);
        aq[s][2] = __float_as_uint(Qs[rl * QPITCH + cq + 8 * s + 4]);
        aq[s][3] = __float_as_uint(Qs[(rl + 8) * QPITCH + cq + 8 * s + 4]);
    }
    __syncwarp();

    float m0 = -1e4f, m1 = -1e4f, l0 = 0.f, l1 = 0.f;
    float oacc[8][4];
#pragma unroll
    for (int d = 0; d < 8; d++)
#pragma unroll
        for (int r = 0; r < 4; r++) oacc[d][r] = 0.f;

    float* Pw = Qs + (w << 4) * QPITCH;
    const int cw = (w >= 4) ? 1 : 0;

    for (int ci = 0; ci < 3; ci++) {
        const int kbase = (cw + ci) * 64;

        float sacc[8][4];
#pragma unroll
        for (int j = 0; j < 8; j++)
#pragma unroll
            for (int r = 0; r < 4; r++) sacc[j][r] = 0.f;

        const float* kb[8];
#pragma unroll
        for (int jt = 0; jt < 8; jt++)
            kb[jt] = Ks + (kbase + 8 * jt + (lane >> 2)) * KPITCH + (lane & 3);

#pragma unroll
        for (int s = 0; s < 8; s++) {
#pragma unroll
            for (int jt = 0; jt < 8; jt++) {
                uint32_t bk[2];
                bk[0] = __float_as_uint(kb[jt][8 * s]);
                bk[1] = __float_as_uint(kb[jt][8 * s + 4]);
                mma_tf32(sacc[jt], aq[s], bk);
            }
        }

        float mx0 = -30000.f, mx1 = -30000.f;
#pragma unroll
        for (int jt = 0; jt < 8; jt++) {
            const int k0 = kbase + 8 * jt + 2 * (lane & 3);
            const int k1 = k0 + 1;
            const int kg0 = kstart + k0, kg1 = kstart + k1;
            const bool in0 = (kg0 >= 0) & (kg0 < SS);
            const bool in1 = (kg1 >= 0) & (kg1 < SS);
            const bool v00 = in0 && ((unsigned)(k0 - rl) <= 128u);
            const bool v01 = in1 && ((unsigned)(k1 - rl) <= 128u);
            const bool v10 = in0 && ((unsigned)(k0 - rl - 8) <= 128u);
            const bool v11 = in1 && ((unsigned)(k1 - rl - 8) <= 128u);
            sacc[jt][0] = v00 ? sacc[jt][0] : -30000.f;
            sacc[jt][1] = v01 ? sacc[jt][1] : -30000.f;
            sacc[jt][2] = v10 ? sacc[jt][2] : -30000.f;
            sacc[jt][3] = v11 ? sacc[jt][3] : -30000.f;
            mx0 = fmaxf(mx0, fmaxf(sacc[jt][0], sacc[jt][1]));
            mx1 = fmaxf(mx1, fmaxf(sacc[jt][2], sacc[jt][3]));
        }
        mx0 = fmaxf(mx0, __shfl_xor_sync(0xffffffff, mx0, 1));
        mx0 = fmaxf(mx0, __shfl_xor_sync(0xffffffff, mx0, 2));
        mx1 = fmaxf(mx1, __shfl_xor_sync(0xffffffff, mx1, 1));
        mx1 = fmaxf(mx1, __shfl_xor_sync(0xffffffff, mx1, 2));

        const float m0n = fmaxf(m0, mx0);
        const float m1n = fmaxf(m1, mx1);
        const float a0 = exp2f(m0 - m0n);
        const float a1 = exp2f(m1 - m1n);
        m0 = m0n; m1 = m1n;
        l0 *= a0; l1 *= a1;
#pragma unroll
        for (int d = 0; d < 8; d++) {
            oacc[d][0] *= a0; oacc[d][1] *= a0;
            oacc[d][2] *= a1; oacc[d][3] *= a1;
        }

        float rs0 = 0.f, rs1 = 0.f;
        const int prow = (lane >> 2);
#pragma unroll
        for (int jt = 0; jt < 8; jt++) {
            float p00 = to_tf32(exp2f(sacc[jt][0] - m0));
            float p01 = to_tf32(exp2f(sacc[jt][1] - m0));
            float p10 = to_tf32(exp2f(sacc[jt][2] - m1));
            float p11 = to_tf32(exp2f(sacc[jt][3] - m1));
            rs0 += p00 + p01;
            rs1 += p10 + p11;
            const int pc = 8 * jt + 2 * (lane & 3);
            *(float2*)(Pw + prow * QPITCH + pc)       = make_float2(p00, p01);
            *(float2*)(Pw + (prow + 8) * QPITCH + pc) = make_float2(p10, p11);
        }
        rs0 += __shfl_xor_sync(0xffffffff, rs0, 1);
        rs0 += __shfl_xor_sync(0xffffffff, rs0, 2);
        rs1 += __shfl_xor_sync(0xffffffff, rs1, 1);
        rs1 += __shfl_xor_sync(0xffffffff, rs1, 2);
        l0 += rs0; l1 += rs1;
        __syncwarp();

#pragma unroll
        for (int s = 0; s < 8; s++) {
            uint32_t pa[4];
            const float* pb = Pw + prow * QPITCH + (lane & 3) + 8 * s;
            pa[0] = __float_as_uint(pb[0]);
            pa[1] = __float_as_uint(pb[8 * QPITCH]);
            pa[2] = __float_as_uint(pb[4]);
            pa[3] = __float_as_uint(pb[8 * QPITCH + 4]);
            const float* vb = Vs + (kbase + 8 * s + (lane & 3)) * VPITCH + (lane >> 2);
#pragma unroll
            for (int dt = 0; dt < 8; dt++) {
                uint32_t bv[2];
                bv[0] = __float_as_uint(vb[8 * dt]);
                bv[1] = __float_as_uint(vb[4 * VPITCH + 8 * dt]);
                mma_tf32(oacc[dt], pa, bv);
            }
        }
        __syncwarp();
    }

    const float inv0 = 1.f / l0;
    const float inv1 = 1.f / l1;
    const int rg = qb * 128 + rl;
    float* og0 = g_attn + ((size_t)(b * SS + rg)) * DD + h * HDIM;
    float* og1 = og0 + 8 * DD;
#pragma unroll
    for (int dt = 0; dt < 8; dt++) {
        const int col = 8 * dt + 2 * (lane & 3);
        *(float2*)(og0 + col) = make_float2(oacc[dt][0] * inv0, oacc[dt][1] * inv0);
        *(float2*)(og1 + col) = make_float2(oacc[dt][2] * inv1, oacc[dt][3] * inv1);
    }
}

// ---------------------------------------------------------------------------
extern "C" void kernel_launch(void* const* d_in, const int* in_sizes, int n_in,
                              void* d_out, int out_size)
{
    const float* hidden = (const float*)d_in[0];
    const float* wqkv   = (const float*)d_in[1];
    const float* wo     = (const float*)d_in[2];
    const int*   pos    = (const int*)d_in[4];
    float*       out    = (float*)d_out;

    float  *qkv_p, *attn_p;
    __half *hidH_p, *attnH_p, *wqH_p, *woH_p;
    cudaGetSymbolAddress((void**)&qkv_p,   g_qkv);
    cudaGetSymbolAddress((void**)&attn_p,  g_attn);
    cudaGetSymbolAddress((void**)&hidH_p,  g_hidH);
    cudaGetSymbolAddress((void**)&attnH_p, g_attnH);
    cudaGetSymbolAddress((void**)&wqH_p,   g_wqH);
    cudaGetSymbolAddress((void**)&woH_p,   g_woH);

    cudaFuncSetAttribute(gemm_h,   cudaFuncAttributeMaxDynamicSharedMemorySize, GEMM_SMEM);
    cudaFuncSetAttribute(attn_mma, cudaFuncAttributeMaxDynamicSharedMemorySize, ATTN_SMEM);

    // 0) RoPE table + operand transforms (fp16 tile images)
    rope_table<<<(NTOK * 32 + 255) / 256, 256>>>(pos);
    xform_a_h<<<(NTOK * DD / 4 + 255) / 256, 256>>>(hidden, hidH_p, NTOK, DD);
    xform_b_h<<<(QKVD * DD / 4 + 255) / 256, 256>>>(wqkv, wqH_p, QKVD, DD);
    xform_b_h<<<(DD * DD / 4 + 255) / 256, 256>>>(wo, woH_p, DD, DD);

    // 1) QKV = hidden @ Wqkv^T   [4096, 2304] row-major fp32
    gemm_h<<<dim3(QKVD / 128, NTOK / 128), 256, GEMM_SMEM>>>(hidH_p, wqH_p, qkv_p,
                                                             QKVD, DD / 32);
    // 2) fused RoPE + sliding-window attention -> g_attn (row-major fp32)
    attn_mma<<<dim3(SS / 128, BB * HH), 256, ATTN_SMEM>>>();
    // 2b) re-image attn output (fp16) for Wo GEMM
    xform_a_h<<<(NTOK * DD / 4 + 255) / 256, 256>>>(attn_p, attnH_p, NTOK, DD);
    // 3) out = attn @ Wo^T       [4096, 768] row-major fp32
    gemm_h<<<dim3(DD / 128, NTOK / 128), 256, GEMM_SMEM>>>(attnH_p, woH_p, out,
                                                           DD, DD / 32);
}

// round 9
// speedup vs baseline: 1.5107x; 1.0964x over previous
#include <cuda_runtime.h>
#include <cuda_fp16.h>
#include <math.h>
#include <stdint.h>

// Problem constants
#define BB   2
#define SS   2048
#define DD   768
#define HH   12
#define HDIM 64
#define QKVD 2304           // 3*D per token
#define NTOK (BB*SS)        // 4096

// Scratch (allocation-free rule: __device__ globals)
__device__ float  g_qkv[(size_t)NTOK * QKVD];   // [4096, 2304] row-major fp32
__device__ float  g_attn[(size_t)NTOK * DD];    // attn out, row-major fp32
__device__ float  g_rope[(size_t)NTOK * 64];    // [token][cos32|sin32]
__device__ __half g_hidH[(size_t)NTOK * DD];    // hidden as A-image (fp16)
__device__ __half g_attnH[(size_t)NTOK * DD];   // attn out as A-image (fp16)
__device__ __half g_wqH[(size_t)QKVD * DD];     // Wqkv as B-image (fp16)
__device__ __half g_woH[(size_t)DD * DD];       // Wo as B-image (fp16)

__device__ __forceinline__ uint32_t smem_u32(const void* p) {
    uint32_t a;
    asm("{ .reg .u64 t; cvta.to.shared.u64 t, %1; cvt.u32.u64 %0, t; }"
        : "=r"(a) : "l"(p));
    return a;
}

__device__ __forceinline__ void mma_f16(float c[4], const uint32_t a[4], const uint32_t b[2]) {
    asm volatile(
        "mma.sync.aligned.m16n8k16.row.col.f32.f16.f16.f32 "
        "{%0,%1,%2,%3}, {%4,%5,%6,%7}, {%8,%9}, {%0,%1,%2,%3};"
        : "+f"(c[0]), "+f"(c[1]), "+f"(c[2]), "+f"(c[3])
        : "r"(a[0]), "r"(a[1]), "r"(a[2]), "r"(a[3]), "r"(b[0]), "r"(b[1]));
}

#define CP_ASYNC16(dst, src) \
    asm volatile("cp.async.cg.shared.global [%0], [%1], 16;" :: "r"(dst), "l"(src))
#define CP_COMMIT() asm volatile("cp.async.commit_group;" ::: "memory")
#define CP_WAIT3()  asm volatile("cp.async.wait_group 3;"  ::: "memory")

// ---------------------------------------------------------------------------
// fp16 tile-image layouts. Tile: 128 rows x 32 k-cols = 4096 halves (8 KB).
// ---------------------------------------------------------------------------
__device__ __forceinline__ size_t aimg_off_h(int r, int k, int ntileK) {
    const int mt = r >> 7, kc = k >> 5;
    const int mi = (r >> 4) & 7, rr = r & 15;
    const int ki = (k >> 4) & 1, kk = k & 15;
    const int lane = ((rr & 7) << 2) + ((kk & 7) >> 1);
    const int e = (kk & 1) + ((rr >> 3) << 1) + ((kk >> 3) << 2);
    return ((size_t)(mt * ntileK + kc) << 12) + (((mi << 1) + ki) << 8) + (lane << 3) + e;
}
__device__ __forceinline__ size_t bimg_off_h(int n, int k, int ntileK) {
    const int nt = n >> 7, kc = k >> 5;
    const int pr = (n >> 4) & 7, p = (n >> 3) & 1, nn = n & 7;
    const int ki = (k >> 4) & 1, kk = k & 15;
    const int lane = (nn << 2) + ((kk & 7) >> 1);
    const int e = (kk & 1) + ((kk >> 3) << 1) + (p << 2);
    return ((size_t)(nt * ntileK + kc) << 12) + (((pr << 1) + ki) << 8) + (lane << 3) + e;
}

__global__ void xform_a_h(const float* __restrict__ X, __half* __restrict__ img, int R, int K)
{
    const int idx = blockIdx.x * 256 + threadIdx.x;
    const int kq = K >> 2;
    if (idx >= R * kq) return;
    const int r = idx / kq, k = (idx - r * kq) << 2;
    const float4 v = *(const float4*)(X + (size_t)r * K + k);
    const int ntileK = K >> 5;
    *(__half2*)(img + aimg_off_h(r, k,     ntileK)) = __floats2half2_rn(v.x, v.y);
    *(__half2*)(img + aimg_off_h(r, k + 2, ntileK)) = __floats2half2_rn(v.z, v.w);
}

__global__ void xform_b_h(const float* __restrict__ X, __half* __restrict__ img, int R, int K)
{
    const int idx = blockIdx.x * 256 + threadIdx.x;
    const int kq = K >> 2;
    if (idx >= R * kq) return;
    const int n = idx / kq, k = (idx - n * kq) << 2;
    const float4 v = *(const float4*)(X + (size_t)n * K + k);
    const int ntileK = K >> 5;
    *(__half2*)(img + bimg_off_h(n, k,     ntileK)) = __floats2half2_rn(v.x, v.y);
    *(__half2*)(img + bimg_off_h(n, k + 2, ntileK)) = __floats2half2_rn(v.z, v.w);
}

// ---------------------------------------------------------------------------
// RoPE table
// ---------------------------------------------------------------------------
__global__ void rope_table(const int* __restrict__ pos_ids)
{
    const int idx = blockIdx.x * 256 + threadIdx.x;
    if (idx >= NTOK * 32) return;
    const int bs = idx >> 5;
    const int d  = idx & 31;
    const float FCOEF = -0.41524101186091903f;
    const float pos = (float)pos_ids[bs];
    const float f = pos * exp2f((float)d * FCOEF);
    float sn, cs;
    sincosf(f, &sn, &cs);
    g_rope[(size_t)bs * 64 + d]      = cs;
    g_rope[(size_t)bs * 64 + 32 + d] = sn;
}

// ---------------------------------------------------------------------------
// fp16 GEMM on tile images (unchanged from round 8).
// ---------------------------------------------------------------------------
#define GEMM_SMEM 65536   // 4 stages x (8KB A + 8KB B)

__global__ __launch_bounds__(256, 2) void gemm_h(const __half* __restrict__ Aimg,
                                                 const __half* __restrict__ Bimg,
                                                 float* __restrict__ C,
                                                 int N, int ntileK)
{
    extern __shared__ __half smh[];
    const uint32_t sbase = smem_u32(smh);
    const int tid    = threadIdx.x;
    const int wid    = tid >> 5;
    const int lane   = tid & 31;
    const int mt     = blockIdx.y;
    const int nt     = blockIdx.x;
    const int warp_m = wid >> 2;
    const int warp_n = wid & 3;

    float acc[4][4][4];
#pragma unroll
    for (int a = 0; a < 4; a++)
#pragma unroll
        for (int b = 0; b < 4; b++)
#pragma unroll
            for (int r = 0; r < 4; r++) acc[a][b][r] = 0.f;

    const int nch = ntileK;
    const __half* Atile0 = Aimg + ((size_t)(mt * ntileK) << 12) + (tid << 3);
    const __half* Btile0 = Bimg + ((size_t)(nt * ntileK) << 12) + (tid << 3);

#define ISSUE(c) do {                                                     \
    if ((c) < nch) {                                                      \
        const __half* As_ = Atile0 + ((size_t)(c) << 12);                 \
        const __half* Bs_ = Btile0 + ((size_t)(c) << 12);                 \
        uint32_t sa_ = sbase + ((c) & 3) * 16384u + (tid << 4);           \
        CP_ASYNC16(sa_,          As_);                                    \
        CP_ASYNC16(sa_ + 4096u,  As_ + 2048);                             \
        CP_ASYNC16(sa_ + 8192u,  Bs_);                                    \
        CP_ASYNC16(sa_ + 12288u, Bs_ + 2048);                             \
    }                                                                     \
    CP_COMMIT();                                                          \
} while (0)

    ISSUE(0); ISSUE(1); ISSUE(2); ISSUE(3);

    const int afo = warp_m * 2048 + lane * 8;
    const int bfo = 4096 + warp_n * 1024 + lane * 8;

    for (int c = 0; c < nch; c++) {
        CP_WAIT3();
        __syncthreads();

        const __half* s = smh + (c & 3) * 8192;
#pragma unroll
        for (int ki = 0; ki < 2; ki++) {
            uint32_t af[4][4], bf[4][2];
#pragma unroll
            for (int a = 0; a < 4; a++) {
                uint4 v = *(const uint4*)(s + afo + a * 512 + ki * 256);
                af[a][0] = v.x; af[a][1] = v.y; af[a][2] = v.z; af[a][3] = v.w;
            }
#pragma unroll
            for (int t = 0; t < 2; t++) {
                uint4 v = *(const uint4*)(s + bfo + t * 512 + ki * 256);
                bf[2*t][0]   = v.x; bf[2*t][1]   = v.y;
                bf[2*t+1][0] = v.z; bf[2*t+1][1] = v.w;
            }
#pragma unroll
            for (int a = 0; a < 4; a++)
#pragma unroll
                for (int b = 0; b < 4; b++)
                    mma_f16(acc[a][b], af[a], bf[b]);
        }
        __syncthreads();
        ISSUE(c + 4);
    }

    const int g = lane >> 2, u = lane & 3;
#pragma unroll
    for (int a = 0; a < 4; a++) {
        const int row = mt * 128 + warp_m * 64 + a * 16 + g;
#pragma unroll
        for (int b = 0; b < 4; b++) {
            const int col = nt * 128 + warp_n * 32 + b * 8 + 2 * u;
            *(float2*)(C + (size_t)row * N + col)       = make_float2(acc[a][b][0], acc[a][b][1]);
            *(float2*)(C + (size_t)(row + 8) * N + col) = make_float2(acc[a][b][2], acc[a][b][3]);
        }
    }
#undef ISSUE
}

// ---------------------------------------------------------------------------
// Fused RoPE (table) + sliding-window attention, fp16 m16n8k16.
// K: Kh[256][72] fp16. V: transposed Vt[64][264] fp16. Q/P: Qh[128][72] fp16.
// ---------------------------------------------------------------------------
#define KPH 72
#define VTP 264
#define QPH 72
#define VT_OFF (256 * KPH)            // 18432 halves
#define QH_OFF (VT_OFF + 64 * VTP)    // 35328 halves
#define ATTN_SMEM ((QH_OFF + 128 * QPH) * 2)   // 89088 bytes

__device__ __forceinline__ void rope4t(float4 cs, float4 sn, float4 x, float4 y,
                                       float4& lo, float4& hi)
{
    lo.x = x.x * cs.x - y.x * sn.x;  hi.x = y.x * cs.x + x.x * sn.x;
    lo.y = x.y * cs.y - y.y * sn.y;  hi.y = y.y * cs.y + x.y * sn.y;
    lo.z = x.z * cs.z - y.z * sn.z;  hi.z = y.z * cs.z + x.z * sn.z;
    lo.w = x.w * cs.w - y.w * sn.w;  hi.w = y.w * cs.w + x.w * sn.w;
}

__global__ __launch_bounds__(256, 2) void attn_mma()
{
    extern __shared__ __half smha[];
    __half* Kh = smha;
    __half* Vt = smha + VT_OFF;
    __half* Qh = smha + QH_OFF;

    const int tid  = threadIdx.x;
    const int lane = tid & 31;
    const int w    = tid >> 5;
    const int g    = lane >> 2;
    const int t    = lane & 3;
    const int qb   = blockIdx.x;
    const int bh   = blockIdx.y;
    const int b    = bh / HH;
    const int h    = bh % HH;
    const int kstart = qb * 128 - 64;

    // ---- Phase A: stage K (RoPE->fp16), V (fp16 transposed), Q (RoPE,scaled) ----
    {
        const int r  = tid;                // one K/V row per thread
        const int kg = kstart + r;
        __half* kd = Kh + r * KPH;
        if (kg >= 0 && kg < SS) {
            const float* kp = g_qkv + ((size_t)(b * SS + kg)) * QKVD + DD + h * HDIM;
            const float* vp = kp + DD;
            const float* rp = g_rope + ((size_t)(b * SS + kg)) * 64;
            __half2 hbuf[32];
#pragma unroll
            for (int i = 0; i < 8; i++) {
                float4 x  = ((const float4*)kp)[i];
                float4 y  = ((const float4*)kp)[i + 8];
                float4 cs = ((const float4*)rp)[i];
                float4 sn = ((const float4*)rp)[i + 8];
                float4 lo, hi;
                rope4t(cs, sn, x, y, lo, hi);
                hbuf[i * 2]      = __floats2half2_rn(lo.x, lo.y);
                hbuf[i * 2 + 1]  = __floats2half2_rn(lo.z, lo.w);
                hbuf[16 + i * 2] = __floats2half2_rn(hi.x, hi.y);
                hbuf[17 + i * 2] = __floats2half2_rn(hi.z, hi.w);
            }
#pragma unroll
            for (int j = 0; j < 8; j++)
                ((uint4*)kd)[j] = ((const uint4*)hbuf)[j];
            // V transposed: Vt[dim][key]
#pragma unroll
            for (int i = 0; i < 16; i++) {
                float4 v = ((const float4*)vp)[i];
                Vt[(4 * i + 0) * VTP + r] = __float2half_rn(v.x);
                Vt[(4 * i + 1) * VTP + r] = __float2half_rn(v.y);
                Vt[(4 * i + 2) * VTP + r] = __float2half_rn(v.z);
                Vt[(4 * i + 3) * VTP + r] = __float2half_rn(v.w);
            }
        } else {
            const uint4 z = make_uint4(0, 0, 0, 0);
#pragma unroll
            for (int j = 0; j < 8; j++)
                ((uint4*)kd)[j] = z;
#pragma unroll
            for (int d = 0; d < 64; d++)
                Vt[d * VTP + r] = __float2half_rn(0.f);
        }
        if (tid < 128) {
            const int qg = qb * 128 + tid;
            const float* qp = g_qkv + ((size_t)(b * SS + qg)) * QKVD + h * HDIM;
            const float* rp = g_rope + ((size_t)(b * SS + qg)) * 64;
            __half* qd = Qh + tid * QPH;
            const float QSC = 0.125f * 1.4426950408889634f;  // scale * log2(e)
            __half2 hbuf[32];
#pragma unroll
            for (int i = 0; i < 8; i++) {
                float4 x  = ((const float4*)qp)[i];
                float4 y  = ((const float4*)qp)[i + 8];
                float4 cs = ((const float4*)rp)[i];
                float4 sn = ((const float4*)rp)[i + 8];
                float4 lo, hi;
                rope4t(cs, sn, x, y, lo, hi);
                hbuf[i * 2]      = __floats2half2_rn(lo.x * QSC, lo.y * QSC);
                hbuf[i * 2 + 1]  = __floats2half2_rn(lo.z * QSC, lo.w * QSC);
                hbuf[16 + i * 2] = __floats2half2_rn(hi.x * QSC, hi.y * QSC);
                hbuf[17 + i * 2] = __floats2half2_rn(hi.z * QSC, hi.w * QSC);
            }
#pragma unroll
            for (int j = 0; j < 8; j++)
                ((uint4*)qd)[j] = ((const uint4*)hbuf)[j];
        }
    }
    __syncthreads();

    // ---- Q A-fragments (fp16, 4 k16-steps) ----
    const int rl = (w << 4) + g;            // low local q-row of this lane
    uint32_t aq[4][4];
#pragma unroll
    for (int s = 0; s < 4; s++) {
        aq[s][0] = *(const uint32_t*)(Qh + rl * QPH + 16 * s + 2 * t);
        aq[s][1] = *(const uint32_t*)(Qh + (rl + 8) * QPH + 16 * s + 2 * t);
        aq[s][2] = *(const uint32_t*)(Qh + rl * QPH + 16 * s + 8 + 2 * t);
        aq[s][3] = *(const uint32_t*)(Qh + (rl + 8) * QPH + 16 * s + 8 + 2 * t);
    }
    __syncwarp();

    float m0 = -1e4f, m1 = -1e4f, l0 = 0.f, l1 = 0.f;
    float oacc[8][4];
#pragma unroll
    for (int d = 0; d < 8; d++)
#pragma unroll
        for (int r = 0; r < 4; r++) oacc[d][r] = 0.f;

    __half* Pw = Qh + (w << 4) * QPH;       // per-warp P region (reuses Q rows)
    const int cw = (w >= 4) ? 1 : 0;

    for (int ci = 0; ci < 3; ci++) {
        const int kbase = (cw + ci) * 64;

        // ---- S = Q @ K^T over this 64-key chunk (fp16 MMA) ----
        float sacc[8][4];
#pragma unroll
        for (int j = 0; j < 8; j++)
#pragma unroll
            for (int r = 0; r < 4; r++) sacc[j][r] = 0.f;

#pragma unroll
        for (int s = 0; s < 4; s++) {
#pragma unroll
            for (int jt = 0; jt < 8; jt++) {
                const __half* kp_ = Kh + (kbase + 8 * jt + g) * KPH + 16 * s;
                uint32_t bk[2];
                bk[0] = *(const uint32_t*)(kp_ + 2 * t);
                bk[1] = *(const uint32_t*)(kp_ + 8 + 2 * t);
                mma_f16(sacc[jt], aq[s], bk);
            }
        }

        // ---- mask + per-row chunk max ----
        float mx0 = -30000.f, mx1 = -30000.f;
#pragma unroll
        for (int jt = 0; jt < 8; jt++) {
            const int k0 = kbase + 8 * jt + 2 * t;
            const int k1 = k0 + 1;
            const int kg0 = kstart + k0, kg1 = kstart + k1;
            const bool in0 = (kg0 >= 0) & (kg0 < SS);
            const bool in1 = (kg1 >= 0) & (kg1 < SS);
            const bool v00 = in0 && ((unsigned)(k0 - rl) <= 128u);
            const bool v01 = in1 && ((unsigned)(k1 - rl) <= 128u);
            const bool v10 = in0 && ((unsigned)(k0 - rl - 8) <= 128u);
            const bool v11 = in1 && ((unsigned)(k1 - rl - 8) <= 128u);
            sacc[jt][0] = v00 ? sacc[jt][0] : -30000.f;
            sacc[jt][1] = v01 ? sacc[jt][1] : -30000.f;
            sacc[jt][2] = v10 ? sacc[jt][2] : -30000.f;
            sacc[jt][3] = v11 ? sacc[jt][3] : -30000.f;
            mx0 = fmaxf(mx0, fmaxf(sacc[jt][0], sacc[jt][1]));
            mx1 = fmaxf(mx1, fmaxf(sacc[jt][2], sacc[jt][3]));
        }
        mx0 = fmaxf(mx0, __shfl_xor_sync(0xffffffff, mx0, 1));
        mx0 = fmaxf(mx0, __shfl_xor_sync(0xffffffff, mx0, 2));
        mx1 = fmaxf(mx1, __shfl_xor_sync(0xffffffff, mx1, 1));
        mx1 = fmaxf(mx1, __shfl_xor_sync(0xffffffff, mx1, 2));

        const float m0n = fmaxf(m0, mx0);
        const float m1n = fmaxf(m1, mx1);
        const float a0 = exp2f(m0 - m0n);
        const float a1 = exp2f(m1 - m1n);
        m0 = m0n; m1 = m1n;
        l0 *= a0; l1 *= a1;
#pragma unroll
        for (int d = 0; d < 8; d++) {
            oacc[d][0] *= a0; oacc[d][1] *= a0;
            oacc[d][2] *= a1; oacc[d][3] *= a1;
        }

        // ---- p = exp2(s - m), fp16-rounded; store to Pw; row-sums ----
        float rs0 = 0.f, rs1 = 0.f;
#pragma unroll
        for (int jt = 0; jt < 8; jt++) {
            __half2 hp0 = __floats2half2_rn(exp2f(sacc[jt][0] - m0),
                                            exp2f(sacc[jt][1] - m0));
            __half2 hp1 = __floats2half2_rn(exp2f(sacc[jt][2] - m1),
                                            exp2f(sacc[jt][3] - m1));
            float2 f0 = __half22float2(hp0);
            float2 f1 = __half22float2(hp1);
            rs0 += f0.x + f0.y;
            rs1 += f1.x + f1.y;
            const int pc = 8 * jt + 2 * t;
            *(__half2*)(Pw + g * QPH + pc)       = hp0;
            *(__half2*)(Pw + (g + 8) * QPH + pc) = hp1;
        }
        rs0 += __shfl_xor_sync(0xffffffff, rs0, 1);
        rs0 += __shfl_xor_sync(0xffffffff, rs0, 2);
        rs1 += __shfl_xor_sync(0xffffffff, rs1, 1);
        rs1 += __shfl_xor_sync(0xffffffff, rs1, 2);
        l0 += rs0; l1 += rs1;
        __syncwarp();

        // ---- O += P @ V  (fp16 MMA, V transposed in smem) ----
#pragma unroll
        for (int s = 0; s < 4; s++) {
            uint32_t pa[4];
            pa[0] = *(const uint32_t*)(Pw + g * QPH + 16 * s + 2 * t);
            pa[1] = *(const uint32_t*)(Pw + (g + 8) * QPH + 16 * s + 2 * t);
            pa[2] = *(const uint32_t*)(Pw + g * QPH + 16 * s + 8 + 2 * t);
            pa[3] = *(const uint32_t*)(Pw + (g + 8) * QPH + 16 * s + 8 + 2 * t);
#pragma unroll
            for (int dt = 0; dt < 8; dt++) {
                const __half* vp_ = Vt + (8 * dt + g) * VTP + kbase + 16 * s;
                uint32_t bv[2];
                bv[0] = *(const uint32_t*)(vp_ + 2 * t);
                bv[1] = *(const uint32_t*)(vp_ + 8 + 2 * t);
                mma_f16(oacc[dt], pa, bv);
            }
        }
        __syncwarp();
    }

    // ---- normalize + coalesced row-major write ----
    const float inv0 = 1.f / l0;
    const float inv1 = 1.f / l1;
    const int rg = qb * 128 + rl;
    float* og0 = g_attn + ((size_t)(b * SS + rg)) * DD + h * HDIM;
    float* og1 = og0 + 8 * DD;
#pragma unroll
    for (int dt = 0; dt < 8; dt++) {
        const int col = 8 * dt + 2 * t;
        *(float2*)(og0 + col) = make_float2(oacc[dt][0] * inv0, oacc[dt][1] * inv0);
        *(float2*)(og1 + col) = make_float2(oacc[dt][2] * inv1, oacc[dt][3] * inv1);
    }
}

// ---------------------------------------------------------------------------
extern "C" void kernel_launch(void* const* d_in, const int* in_sizes, int n_in,
                              void* d_out, int out_size)
{
    const float* hidden = (const float*)d_in[0];
    const float* wqkv   = (const float*)d_in[1];
    const float* wo     = (const float*)d_in[2];
    const int*   pos    = (const int*)d_in[4];
    float*       out    = (float*)d_out;

    float  *qkv_p, *attn_p;
    __half *hidH_p, *attnH_p, *wqH_p, *woH_p;
    cudaGetSymbolAddress((void**)&qkv_p,   g_qkv);
    cudaGetSymbolAddress((void**)&attn_p,  g_attn);
    cudaGetSymbolAddress((void**)&hidH_p,  g_hidH);
    cudaGetSymbolAddress((void**)&attnH_p, g_attnH);
    cudaGetSymbolAddress((void**)&wqH_p,   g_wqH);
    cudaGetSymbolAddress((void**)&woH_p,   g_woH);

    cudaFuncSetAttribute(gemm_h,   cudaFuncAttributeMaxDynamicSharedMemorySize, GEMM_SMEM);
    cudaFuncSetAttribute(attn_mma, cudaFuncAttributeMaxDynamicSharedMemorySize, ATTN_SMEM);

    // 0) RoPE table + operand transforms (fp16 tile images)
    rope_table<<<(NTOK * 32 + 255) / 256, 256>>>(pos);
    xform_a_h<<<(NTOK * DD / 4 + 255) / 256, 256>>>(hidden, hidH_p, NTOK, DD);
    xform_b_h<<<(QKVD * DD / 4 + 255) / 256, 256>>>(wqkv, wqH_p, QKVD, DD);
    xform_b_h<<<(DD * DD / 4 + 255) / 256, 256>>>(wo, woH_p, DD, DD);

    // 1) QKV = hidden @ Wqkv^T   [4096, 2304] row-major fp32
    gemm_h<<<dim3(QKVD / 128, NTOK / 128), 256, GEMM_SMEM>>>(hidH_p, wqH_p, qkv_p,
                                                             QKVD, DD / 32);
    // 2) fused RoPE + sliding-window attention (fp16 MMA) -> g_attn
    attn_mma<<<dim3(SS / 128, BB * HH), 256, ATTN_SMEM>>>();
    // 2b) re-image attn output (fp16) for Wo GEMM
    xform_a_h<<<(NTOK * DD / 4 + 255) / 256, 256>>>(attn_p, attnH_p, NTOK, DD);
    // 3) out = attn @ Wo^T       [4096, 768] row-major fp32
    gemm_h<<<dim3(DD / 128, NTOK / 128), 256, GEMM_SMEM>>>(attnH_p, woH_p, out,
                                                           DD, DD / 32);
}

// round 10
// speedup vs baseline: 1.6140x; 1.0684x over previous
#include <cuda_runtime.h>
#include <cuda_fp16.h>
#include <math.h>
#include <stdint.h>

// Problem constants
#define BB   2
#define SS   2048
#define DD   768
#define HH   12
#define HDIM 64
#define QKVD 2304           // 3*D per token
#define NTOK (BB*SS)        // 4096

// Scratch (allocation-free rule: __device__ globals)
__device__ float  g_qkv[(size_t)NTOK * QKVD];   // [4096, 2304] row-major fp32
__device__ float  g_attn[(size_t)NTOK * DD];    // attn out, row-major fp32
__device__ float  g_rope[(size_t)NTOK * 64];    // [token][cos32|sin32]
__device__ __half g_hidH[(size_t)NTOK * DD];    // hidden as A-image (fp16)
__device__ __half g_attnH[(size_t)NTOK * DD];   // attn out as A-image (fp16)
__device__ __half g_wqH[(size_t)QKVD * DD];     // Wqkv as B-image (fp16)
__device__ __half g_woH[(size_t)DD * DD];       // Wo as B-image (fp16)

__device__ __forceinline__ uint32_t smem_u32(const void* p) {
    uint32_t a;
    asm("{ .reg .u64 t; cvta.to.shared.u64 t, %1; cvt.u32.u64 %0, t; }"
        : "=r"(a) : "l"(p));
    return a;
}

__device__ __forceinline__ void mma_f16(float c[4], const uint32_t a[4], const uint32_t b[2]) {
    asm volatile(
        "mma.sync.aligned.m16n8k16.row.col.f32.f16.f16.f32 "
        "{%0,%1,%2,%3}, {%4,%5,%6,%7}, {%8,%9}, {%0,%1,%2,%3};"
        : "+f"(c[0]), "+f"(c[1]), "+f"(c[2]), "+f"(c[3])
        : "r"(a[0]), "r"(a[1]), "r"(a[2]), "r"(a[3]), "r"(b[0]), "r"(b[1]));
}

#define LDSM_X4(r0,r1,r2,r3,a) \
    asm volatile("ldmatrix.sync.aligned.m8n8.x4.shared.b16 {%0,%1,%2,%3}, [%4];" \
                 : "=r"(r0), "=r"(r1), "=r"(r2), "=r"(r3) : "r"(a))
#define LDSM_X4T(r0,r1,r2,r3,a) \
    asm volatile("ldmatrix.sync.aligned.m8n8.x4.trans.shared.b16 {%0,%1,%2,%3}, [%4];" \
                 : "=r"(r0), "=r"(r1), "=r"(r2), "=r"(r3) : "r"(a))

#define CP_ASYNC16(dst, src) \
    asm volatile("cp.async.cg.shared.global [%0], [%1], 16;" :: "r"(dst), "l"(src))
#define CP_COMMIT() asm volatile("cp.async.commit_group;" ::: "memory")
#define CP_WAIT3()  asm volatile("cp.async.wait_group 3;"  ::: "memory")

// ---------------------------------------------------------------------------
// fp16 tile-image layouts. Tile: 128 rows x 32 k-cols = 4096 halves (8 KB).
// ---------------------------------------------------------------------------
__device__ __forceinline__ size_t aimg_off_h(int r, int k, int ntileK) {
    const int mt = r >> 7, kc = k >> 5;
    const int mi = (r >> 4) & 7, rr = r & 15;
    const int ki = (k >> 4) & 1, kk = k & 15;
    const int lane = ((rr & 7) << 2) + ((kk & 7) >> 1);
    const int e = (kk & 1) + ((rr >> 3) << 1) + ((kk >> 3) << 2);
    return ((size_t)(mt * ntileK + kc) << 12) + (((mi << 1) + ki) << 8) + (lane << 3) + e;
}
__device__ __forceinline__ size_t bimg_off_h(int n, int k, int ntileK) {
    const int nt = n >> 7, kc = k >> 5;
    const int pr = (n >> 4) & 7, p = (n >> 3) & 1, nn = n & 7;
    const int ki = (k >> 4) & 1, kk = k & 15;
    const int lane = (nn << 2) + ((kk & 7) >> 1);
    const int e = (kk & 1) + ((kk >> 3) << 1) + (p << 2);
    return ((size_t)(nt * ntileK + kc) << 12) + (((pr << 1) + ki) << 8) + (lane << 3) + e;
}

__device__ __forceinline__ void xform_a_body(int idx, const float* __restrict__ X,
                                             __half* __restrict__ img, int K)
{
    const int kq = K >> 2;
    const int r = idx / kq, k = (idx - r * kq) << 2;
    const float4 v = *(const float4*)(X + (size_t)r * K + k);
    const int ntileK = K >> 5;
    *(__half2*)(img + aimg_off_h(r, k,     ntileK)) = __floats2half2_rn(v.x, v.y);
    *(__half2*)(img + aimg_off_h(r, k + 2, ntileK)) = __floats2half2_rn(v.z, v.w);
}

__device__ __forceinline__ void xform_b_body(int idx, const float* __restrict__ X,
                                             __half* __restrict__ img, int K)
{
    const int kq = K >> 2;
    const int n = idx / kq, k = (idx - n * kq) << 2;
    const float4 v = *(const float4*)(X + (size_t)n * K + k);
    const int ntileK = K >> 5;
    *(__half2*)(img + bimg_off_h(n, k,     ntileK)) = __floats2half2_rn(v.x, v.y);
    *(__half2*)(img + bimg_off_h(n, k + 2, ntileK)) = __floats2half2_rn(v.z, v.w);
}

// ---------------------------------------------------------------------------
// Fused prologue: RoPE table + all operand image transforms in one launch.
// Region dispatch over blockIdx.x: [0,512) rope, [512,3584) hidden-A,
// [3584,5312) Wqkv-B, [5312,5888) Wo-B.
// ---------------------------------------------------------------------------
__global__ void prologue(const float* __restrict__ hidden,
                         const float* __restrict__ wqkv,
                         const float* __restrict__ wo,
                         const int*   __restrict__ pos_ids)
{
    const int bid = blockIdx.x;
    if (bid < 512) {
        const int idx = bid * 256 + threadIdx.x;          // NTOK*32
        const int bs = idx >> 5;
        const int d  = idx & 31;
        const float FCOEF = -0.41524101186091903f;
        const float pos = (float)pos_ids[bs];
        const float f = pos * exp2f((float)d * FCOEF);
        float sn, cs;
        sincosf(f, &sn, &cs);
        g_rope[(size_t)bs * 64 + d]      = cs;
        g_rope[(size_t)bs * 64 + 32 + d] = sn;
    } else if (bid < 3584) {
        xform_a_body((bid - 512) * 256 + threadIdx.x, hidden, g_hidH, DD);
    } else if (bid < 5312) {
        xform_b_body((bid - 3584) * 256 + threadIdx.x, wqkv, g_wqH, DD);
    } else {
        xform_b_body((bid - 5312) * 256 + threadIdx.x, wo, g_woH, DD);
    }
}

// Standalone A-image transform (attn output re-image before Wo GEMM)
__global__ void xform_a_h(const float* __restrict__ X, __half* __restrict__ img, int R, int K)
{
    const int idx = blockIdx.x * 256 + threadIdx.x;
    if (idx >= R * (K >> 2)) return;
    xform_a_body(idx, X, img, K);
}

// ---------------------------------------------------------------------------
// fp16 GEMM on tile images (unchanged from round 8/9).
// ---------------------------------------------------------------------------
#define GEMM_SMEM 65536   // 4 stages x (8KB A + 8KB B)

__global__ __launch_bounds__(256, 2) void gemm_h(const __half* __restrict__ Aimg,
                                                 const __half* __restrict__ Bimg,
                                                 float* __restrict__ C,
                                                 int N, int ntileK)
{
    extern __shared__ __half smh[];
    const uint32_t sbase = smem_u32(smh);
    const int tid    = threadIdx.x;
    const int wid    = tid >> 5;
    const int lane   = tid & 31;
    const int mt     = blockIdx.y;
    const int nt     = blockIdx.x;
    const int warp_m = wid >> 2;
    const int warp_n = wid & 3;

    float acc[4][4][4];
#pragma unroll
    for (int a = 0; a < 4; a++)
#pragma unroll
        for (int b = 0; b < 4; b++)
#pragma unroll
            for (int r = 0; r < 4; r++) acc[a][b][r] = 0.f;

    const int nch = ntileK;
    const __half* Atile0 = Aimg + ((size_t)(mt * ntileK) << 12) + (tid << 3);
    const __half* Btile0 = Bimg + ((size_t)(nt * ntileK) << 12) + (tid << 3);

#define ISSUE(c) do {                                                     \
    if ((c) < nch) {                                                      \
        const __half* As_ = Atile0 + ((size_t)(c) << 12);                 \
        const __half* Bs_ = Btile0 + ((size_t)(c) << 12);                 \
        uint32_t sa_ = sbase + ((c) & 3) * 16384u + (tid << 4);           \
        CP_ASYNC16(sa_,          As_);                                    \
        CP_ASYNC16(sa_ + 4096u,  As_ + 2048);                             \
        CP_ASYNC16(sa_ + 8192u,  Bs_);                                    \
        CP_ASYNC16(sa_ + 12288u, Bs_ + 2048);                             \
    }                                                                     \
    CP_COMMIT();                                                          \
} while (0)

    ISSUE(0); ISSUE(1); ISSUE(2); ISSUE(3);

    const int afo = warp_m * 2048 + lane * 8;
    const int bfo = 4096 + warp_n * 1024 + lane * 8;

    for (int c = 0; c < nch; c++) {
        CP_WAIT3();
        __syncthreads();

        const __half* s = smh + (c & 3) * 8192;
#pragma unroll
        for (int ki = 0; ki < 2; ki++) {
            uint32_t af[4][4], bf[4][2];
#pragma unroll
            for (int a = 0; a < 4; a++) {
                uint4 v = *(const uint4*)(s + afo + a * 512 + ki * 256);
                af[a][0] = v.x; af[a][1] = v.y; af[a][2] = v.z; af[a][3] = v.w;
            }
#pragma unroll
            for (int t = 0; t < 2; t++) {
                uint4 v = *(const uint4*)(s + bfo + t * 512 + ki * 256);
                bf[2*t][0]   = v.x; bf[2*t][1]   = v.y;
                bf[2*t+1][0] = v.z; bf[2*t+1][1] = v.w;
            }
#pragma unroll
            for (int a = 0; a < 4; a++)
#pragma unroll
                for (int b = 0; b < 4; b++)
                    mma_f16(acc[a][b], af[a], bf[b]);
        }
        __syncthreads();
        ISSUE(c + 4);
    }

    const int g = lane >> 2, u = lane & 3;
#pragma unroll
    for (int a = 0; a < 4; a++) {
        const int row = mt * 128 + warp_m * 64 + a * 16 + g;
#pragma unroll
        for (int b = 0; b < 4; b++) {
            const int col = nt * 128 + warp_n * 32 + b * 8 + 2 * u;
            *(float2*)(C + (size_t)row * N + col)       = make_float2(acc[a][b][0], acc[a][b][1]);
            *(float2*)(C + (size_t)(row + 8) * N + col) = make_float2(acc[a][b][2], acc[a][b][3]);
        }
    }
#undef ISSUE
}

// ---------------------------------------------------------------------------
// Fused RoPE (table) + sliding-window attention, fp16 m16n8k16 + ldmatrix.
// Kh[256][72], Vh[256][72] (row-major; transpose via ldmatrix.trans),
// Qh/P[128][72]. All fp16, pitch 72 halves (144B -> LDSM conflict-free).
// ---------------------------------------------------------------------------
#define KPH 72
#define VHP 72
#define QPH 72
#define VH_OFF (256 * KPH)            // 18432 halves
#define QH_OFF (VH_OFF + 256 * VHP)   // 36864 halves
#define ATTN_SMEM ((QH_OFF + 128 * QPH) * 2)   // 92160 bytes

__device__ __forceinline__ void rope4t(float4 cs, float4 sn, float4 x, float4 y,
                                       float4& lo, float4& hi)
{
    lo.x = x.x * cs.x - y.x * sn.x;  hi.x = y.x * cs.x + x.x * sn.x;
    lo.y = x.y * cs.y - y.y * sn.y;  hi.y = y.y * cs.y + x.y * sn.y;
    lo.z = x.z * cs.z - y.z * sn.z;  hi.z = y.z * cs.z + x.z * sn.z;
    lo.w = x.w * cs.w - y.w * sn.w;  hi.w = y.w * cs.w + x.w * sn.w;
}

__global__ __launch_bounds__(256, 2) void attn_mma()
{
    extern __shared__ __half smha[];
    __half* Kh = smha;
    __half* Vh = smha + VH_OFF;
    __half* Qh = smha + QH_OFF;

    const int tid  = threadIdx.x;
    const int lane = tid & 31;
    const int w    = tid >> 5;
    const int g    = lane >> 2;
    const int t    = lane & 3;
    const int j    = lane >> 3;      // ldmatrix matrix index
    const int rim  = lane & 7;       // ldmatrix row-in-matrix
    const int qb   = blockIdx.x;
    const int bh   = blockIdx.y;
    const int b    = bh / HH;
    const int h    = bh % HH;
    const int kstart = qb * 128 - 64;

    // ---- Phase A: stage K (RoPE->fp16), V (fp16 row-major), Q (RoPE,scaled) ----
    {
        const int r  = tid;
        const int kg = kstart + r;
        __half* kd = Kh + r * KPH;
        __half* vd = Vh + r * VHP;
        if (kg >= 0 && kg < SS) {
            const float* kp = g_qkv + ((size_t)(b * SS + kg)) * QKVD + DD + h * HDIM;
            const float* vp = kp + DD;
            const float* rp = g_rope + ((size_t)(b * SS + kg)) * 64;
            __half2 hbuf[32];
#pragma unroll
            for (int i = 0; i < 8; i++) {
                float4 x  = ((const float4*)kp)[i];
                float4 y  = ((const float4*)kp)[i + 8];
                float4 cs = ((const float4*)rp)[i];
                float4 sn = ((const float4*)rp)[i + 8];
                float4 lo, hi;
                rope4t(cs, sn, x, y, lo, hi);
                hbuf[i * 2]      = __floats2half2_rn(lo.x, lo.y);
                hbuf[i * 2 + 1]  = __floats2half2_rn(lo.z, lo.w);
                hbuf[16 + i * 2] = __floats2half2_rn(hi.x, hi.y);
                hbuf[17 + i * 2] = __floats2half2_rn(hi.z, hi.w);
            }
#pragma unroll
            for (int q = 0; q < 8; q++)
                ((uint4*)kd)[q] = ((const uint4*)hbuf)[q];
            // V row-major fp16 (transpose happens in ldmatrix.trans)
            __half2 vbuf[32];
#pragma unroll
            for (int i = 0; i < 16; i++) {
                float4 v = ((const float4*)vp)[i];
                vbuf[2 * i]     = __floats2half2_rn(v.x, v.y);
                vbuf[2 * i + 1] = __floats2half2_rn(v.z, v.w);
            }
#pragma unroll
            for (int q = 0; q < 8; q++)
                ((uint4*)vd)[q] = ((const uint4*)vbuf)[q];
        } else {
            const uint4 z = make_uint4(0, 0, 0, 0);
#pragma unroll
            for (int q = 0; q < 8; q++) {
                ((uint4*)kd)[q] = z;
                ((uint4*)vd)[q] = z;
            }
        }
        if (tid < 128) {
            const int qg = qb * 128 + tid;
            const float* qp = g_qkv + ((size_t)(b * SS + qg)) * QKVD + h * HDIM;
            const float* rp = g_rope + ((size_t)(b * SS + qg)) * 64;
            __half* qd = Qh + tid * QPH;
            const float QSC = 0.125f * 1.4426950408889634f;  // scale * log2(e)
            __half2 hbuf[32];
#pragma unroll
            for (int i = 0; i < 8; i++) {
                float4 x  = ((const float4*)qp)[i];
                float4 y  = ((const float4*)qp)[i + 8];
                float4 cs = ((const float4*)rp)[i];
                float4 sn = ((const float4*)rp)[i + 8];
                float4 lo, hi;
                rope4t(cs, sn, x, y, lo, hi);
                hbuf[i * 2]      = __floats2half2_rn(lo.x * QSC, lo.y * QSC);
                hbuf[i * 2 + 1]  = __floats2half2_rn(lo.z * QSC, lo.w * QSC);
                hbuf[16 + i * 2] = __floats2half2_rn(hi.x * QSC, hi.y * QSC);
                hbuf[17 + i * 2] = __floats2half2_rn(hi.z * QSC, hi.w * QSC);
            }
#pragma unroll
            for (int q = 0; q < 8; q++)
                ((uint4*)qd)[q] = ((const uint4*)hbuf)[q];
        }
    }
    __syncthreads();

    const uint32_t kh_base = smem_u32(Kh);
    const uint32_t vh_base = smem_u32(Vh);
    const uint32_t qh_base = smem_u32(Qh);
    const uint32_t pw_base = qh_base + (uint32_t)((w << 4) * QPH * 2);

    // ---- Q A-fragments via ldmatrix.x4 ----
    const int rl = (w << 4) + g;            // low local q-row of this lane (C-frag rows)
    uint32_t aq[4][4];
    {
        const uint32_t qa = qh_base +
            (uint32_t)((((w << 4) + rim + 8 * (j & 1)) * QPH + 8 * (j >> 1)) * 2);
#pragma unroll
        for (int s = 0; s < 4; s++)
            LDSM_X4(aq[s][0], aq[s][1], aq[s][2], aq[s][3], qa + 32u * s);
    }
    __syncwarp();

    float m0 = -1e4f, m1 = -1e4f, l0 = 0.f, l1 = 0.f;
    float oacc[8][4];
#pragma unroll
    for (int d = 0; d < 8; d++)
#pragma unroll
        for (int r = 0; r < 4; r++) oacc[d][r] = 0.f;

    __half* Pw = Qh + (w << 4) * QPH;       // per-warp P region (reuses Q rows)
    const int cw = (w >= 4) ? 1 : 0;

    // per-thread ldmatrix address bases (byte offsets)
    const uint32_t k_lds0 = kh_base + (uint32_t)(((8 * (j >> 1) + rim) * KPH + 8 * (j & 1)) * 2);
    const uint32_t v_lds0 = vh_base + (uint32_t)(((8 * (j & 1) + rim) * VHP + 8 * (j >> 1)) * 2);
    const uint32_t p_lds0 = pw_base + (uint32_t)(((rim + 8 * (j & 1)) * QPH + 8 * (j >> 1)) * 2);

    for (int ci = 0; ci < 3; ci++) {
        const int kbase = (cw + ci) * 64;

        // ---- S = Q @ K^T (B-frags via ldmatrix.x4) ----
        float sacc[8][4];
#pragma unroll
        for (int q = 0; q < 8; q++)
#pragma unroll
            for (int r = 0; r < 4; r++) sacc[q][r] = 0.f;

#pragma unroll
        for (int s = 0; s < 4; s++) {
#pragma unroll
            for (int jp = 0; jp < 4; jp++) {
                uint32_t r0, r1, r2, r3;
                const uint32_t ka = k_lds0 +
                    (uint32_t)((kbase + 16 * jp) * KPH * 2) + 32u * s;
                LDSM_X4(r0, r1, r2, r3, ka);
                uint32_t b0[2] = {r0, r1};
                uint32_t b1[2] = {r2, r3};
                mma_f16(sacc[2 * jp],     aq[s], b0);
                mma_f16(sacc[2 * jp + 1], aq[s], b1);
            }
        }

        // ---- mask + per-row chunk max ----
        float mx0 = -30000.f, mx1 = -30000.f;
#pragma unroll
        for (int jt = 0; jt < 8; jt++) {
            const int k0 = kbase + 8 * jt + 2 * t;
            const int k1 = k0 + 1;
            const int kg0 = kstart + k0, kg1 = kstart + k1;
            const bool in0 = (kg0 >= 0) & (kg0 < SS);
            const bool in1 = (kg1 >= 0) & (kg1 < SS);
            const bool v00 = in0 && ((unsigned)(k0 - rl) <= 128u);
            const bool v01 = in1 && ((unsigned)(k1 - rl) <= 128u);
            const bool v10 = in0 && ((unsigned)(k0 - rl - 8) <= 128u);
            const bool v11 = in1 && ((unsigned)(k1 - rl - 8) <= 128u);
            sacc[jt][0] = v00 ? sacc[jt][0] : -30000.f;
            sacc[jt][1] = v01 ? sacc[jt][1] : -30000.f;
            sacc[jt][2] = v10 ? sacc[jt][2] : -30000.f;
            sacc[jt][3] = v11 ? sacc[jt][3] : -30000.f;
            mx0 = fmaxf(mx0, fmaxf(sacc[jt][0], sacc[jt][1]));
            mx1 = fmaxf(mx1, fmaxf(sacc[jt][2], sacc[jt][3]));
        }
        mx0 = fmaxf(mx0, __shfl_xor_sync(0xffffffff, mx0, 1));
        mx0 = fmaxf(mx0, __shfl_xor_sync(0xffffffff, mx0, 2));
        mx1 = fmaxf(mx1, __shfl_xor_sync(0xffffffff, mx1, 1));
        mx1 = fmaxf(mx1, __shfl_xor_sync(0xffffffff, mx1, 2));

        const float m0n = fmaxf(m0, mx0);
        const float m1n = fmaxf(m1, mx1);
        const float a0 = exp2f(m0 - m0n);
        const float a1 = exp2f(m1 - m1n);
        m0 = m0n; m1 = m1n;
        l0 *= a0; l1 *= a1;
#pragma unroll
        for (int d = 0; d < 8; d++) {
            oacc[d][0] *= a0; oacc[d][1] *= a0;
            oacc[d][2] *= a1; oacc[d][3] *= a1;
        }

        // ---- p = exp2(s - m), fp16-rounded; store to Pw; row-sums ----
        float rs0 = 0.f, rs1 = 0.f;
#pragma unroll
        for (int jt = 0; jt < 8; jt++) {
            __half2 hp0 = __floats2half2_rn(exp2f(sacc[jt][0] - m0),
                                            exp2f(sacc[jt][1] - m0));
            __half2 hp1 = __floats2half2_rn(exp2f(sacc[jt][2] - m1),
                                            exp2f(sacc[jt][3] - m1));
            float2 f0 = __half22float2(hp0);
            float2 f1 = __half22float2(hp1);
            rs0 += f0.x + f0.y;
            rs1 += f1.x + f1.y;
            const int pc = 8 * jt + 2 * t;
            *(__half2*)(Pw + g * QPH + pc)       = hp0;
            *(__half2*)(Pw + (g + 8) * QPH + pc) = hp1;
        }
        rs0 += __shfl_xor_sync(0xffffffff, rs0, 1);
        rs0 += __shfl_xor_sync(0xffffffff, rs0, 2);
        rs1 += __shfl_xor_sync(0xffffffff, rs1, 1);
        rs1 += __shfl_xor_sync(0xffffffff, rs1, 2);
        l0 += rs0; l1 += rs1;
        __syncwarp();

        // ---- O += P @ V  (A-frag ldmatrix, B-frag ldmatrix.trans on row-major V) ----
#pragma unroll
        for (int s = 0; s < 4; s++) {
            uint32_t pa[4];
            LDSM_X4(pa[0], pa[1], pa[2], pa[3], p_lds0 + 32u * s);
#pragma unroll
            for (int dp = 0; dp < 4; dp++) {
                uint32_t r0, r1, r2, r3;
                const uint32_t va = v_lds0 +
                    (uint32_t)((kbase + 16 * s) * VHP * 2) + 32u * dp;
                LDSM_X4T(r0, r1, r2, r3, va);
                uint32_t b0[2] = {r0, r1};
                uint32_t b1[2] = {r2, r3};
                mma_f16(oacc[2 * dp],     pa, b0);
                mma_f16(oacc[2 * dp + 1], pa, b1);
            }
        }
        __syncwarp();
    }

    // ---- normalize + coalesced row-major write ----
    const float inv0 = 1.f / l0;
    const float inv1 = 1.f / l1;
    const int rg = qb * 128 + rl;
    float* og0 = g_attn + ((size_t)(b * SS + rg)) * DD + h * HDIM;
    float* og1 = og0 + 8 * DD;
#pragma unroll
    for (int dt = 0; dt < 8; dt++) {
        const int col = 8 * dt + 2 * t;
        *(float2*)(og0 + col) = make_float2(oacc[dt][0] * inv0, oacc[dt][1] * inv0);
        *(float2*)(og1 + col) = make_float2(oacc[dt][2] * inv1, oacc[dt][3] * inv1);
    }
}

// ---------------------------------------------------------------------------
extern "C" void kernel_launch(void* const* d_in, const int* in_sizes, int n_in,
                              void* d_out, int out_size)
{
    const float* hidden = (const float*)d_in[0];
    const float* wqkv   = (const float*)d_in[1];
    const float* wo     = (const float*)d_in[2];
    const int*   pos    = (const int*)d_in[4];
    float*       out    = (float*)d_out;

    float  *qkv_p, *attn_p;
    __half *hidH_p, *attnH_p, *wqH_p, *woH_p;
    cudaGetSymbolAddress((void**)&qkv_p,   g_qkv);
    cudaGetSymbolAddress((void**)&attn_p,  g_attn);
    cudaGetSymbolAddress((void**)&hidH_p,  g_hidH);
    cudaGetSymbolAddress((void**)&attnH_p, g_attnH);
    cudaGetSymbolAddress((void**)&wqH_p,   g_wqH);
    cudaGetSymbolAddress((void**)&woH_p,   g_woH);

    cudaFuncSetAttribute(gemm_h,   cudaFuncAttributeMaxDynamicSharedMemorySize, GEMM_SMEM);
    cudaFuncSetAttribute(attn_mma, cudaFuncAttributeMaxDynamicSharedMemorySize, ATTN_SMEM);

    // 0) fused prologue: RoPE table + all operand images (one launch)
    prologue<<<5888, 256>>>(hidden, wqkv, wo, pos);

    // 1) QKV = hidden @ Wqkv^T   [4096, 2304] row-major fp32
    gemm_h<<<dim3(QKVD / 128, NTOK / 128), 256, GEMM_SMEM>>>(hidH_p, wqH_p, qkv_p,
                                                             QKVD, DD / 32);
    // 2) fused RoPE + sliding-window attention (fp16 MMA + ldmatrix) -> g_attn
    attn_mma<<<dim3(SS / 128, BB * HH), 256, ATTN_SMEM>>>();
    // 2b) re-image attn output (fp16) for Wo GEMM
    xform_a_h<<<(NTOK * DD / 4 + 255) / 256, 256>>>(attn_p, attnH_p, NTOK, DD);
    // 3) out = attn @ Wo^T       [4096, 768] row-major fp32
    gemm_h<<<dim3(DD / 128, NTOK / 128), 256, GEMM_SMEM>>>(attnH_p, woH_p, out,
                                                           DD, DD / 32);
}

// round 11
// speedup vs baseline: 1.7325x; 1.0734x over previous
#include <cuda_runtime.h>
#include <cuda_fp16.h>
#include <math.h>
#include <stdint.h>

// Problem constants
#define BB   2
#define SS   2048
#define DD   768
#define HH   12
#define HDIM 64
#define QKVD 2304           // 3*D per token
#define NTOK (BB*SS)        // 4096

// Scratch (allocation-free rule: __device__ globals)
__device__ float  g_qkv[(size_t)NTOK * QKVD];   // [4096, 2304] row-major fp32
__device__ float  g_rope[(size_t)NTOK * 64];    // [token][cos32|sin32]
__device__ __half g_hidH[(size_t)NTOK * DD];    // hidden as A-image (fp16)
__device__ __half g_attnH[(size_t)NTOK * DD];   // attn out as A-image (fp16)
__device__ __half g_wqH[(size_t)QKVD * DD];     // Wqkv as B-image (fp16)
__device__ __half g_woH[(size_t)DD * DD];       // Wo as B-image (fp16)

__device__ __forceinline__ uint32_t smem_u32(const void* p) {
    uint32_t a;
    asm("{ .reg .u64 t; cvta.to.shared.u64 t, %1; cvt.u32.u64 %0, t; }"
        : "=r"(a) : "l"(p));
    return a;
}

__device__ __forceinline__ void mma_f16(float c[4], const uint32_t a[4], const uint32_t b[2]) {
    asm volatile(
        "mma.sync.aligned.m16n8k16.row.col.f32.f16.f16.f32 "
        "{%0,%1,%2,%3}, {%4,%5,%6,%7}, {%8,%9}, {%0,%1,%2,%3};"
        : "+f"(c[0]), "+f"(c[1]), "+f"(c[2]), "+f"(c[3])
        : "r"(a[0]), "r"(a[1]), "r"(a[2]), "r"(a[3]), "r"(b[0]), "r"(b[1]));
}

#define LDSM_X4(r0,r1,r2,r3,a) \
    asm volatile("ldmatrix.sync.aligned.m8n8.x4.shared.b16 {%0,%1,%2,%3}, [%4];" \
                 : "=r"(r0), "=r"(r1), "=r"(r2), "=r"(r3) : "r"(a))
#define LDSM_X4T(r0,r1,r2,r3,a) \
    asm volatile("ldmatrix.sync.aligned.m8n8.x4.trans.shared.b16 {%0,%1,%2,%3}, [%4];" \
                 : "=r"(r0), "=r"(r1), "=r"(r2), "=r"(r3) : "r"(a))

#define CP_ASYNC16(dst, src) \
    asm volatile("cp.async.cg.shared.global [%0], [%1], 16;" :: "r"(dst), "l"(src))
#define CP_COMMIT() asm volatile("cp.async.commit_group;" ::: "memory")
#define CP_WAIT3()  asm volatile("cp.async.wait_group 3;"  ::: "memory")

// ---------------------------------------------------------------------------
// fp16 tile-image layouts. Tile: 128 rows x 32 k-cols = 4096 halves (8 KB).
// ---------------------------------------------------------------------------
__device__ __forceinline__ size_t aimg_off_h(int r, int k, int ntileK) {
    const int mt = r >> 7, kc = k >> 5;
    const int mi = (r >> 4) & 7, rr = r & 15;
    const int ki = (k >> 4) & 1, kk = k & 15;
    const int lane = ((rr & 7) << 2) + ((kk & 7) >> 1);
    const int e = (kk & 1) + ((rr >> 3) << 1) + ((kk >> 3) << 2);
    return ((size_t)(mt * ntileK + kc) << 12) + (((mi << 1) + ki) << 8) + (lane << 3) + e;
}
__device__ __forceinline__ size_t bimg_off_h(int n, int k, int ntileK) {
    const int nt = n >> 7, kc = k >> 5;
    const int pr = (n >> 4) & 7, p = (n >> 3) & 1, nn = n & 7;
    const int ki = (k >> 4) & 1, kk = k & 15;
    const int lane = (nn << 2) + ((kk & 7) >> 1);
    const int e = (kk & 1) + ((kk >> 3) << 1) + (p << 2);
    return ((size_t)(nt * ntileK + kc) << 12) + (((pr << 1) + ki) << 8) + (lane << 3) + e;
}

__device__ __forceinline__ void xform_a_body(int idx, const float* __restrict__ X,
                                             __half* __restrict__ img, int K)
{
    const int kq = K >> 2;
    const int r = idx / kq, k = (idx - r * kq) << 2;
    const float4 v = *(const float4*)(X + (size_t)r * K + k);
    const int ntileK = K >> 5;
    *(__half2*)(img + aimg_off_h(r, k,     ntileK)) = __floats2half2_rn(v.x, v.y);
    *(__half2*)(img + aimg_off_h(r, k + 2, ntileK)) = __floats2half2_rn(v.z, v.w);
}

__device__ __forceinline__ void xform_b_body(int idx, const float* __restrict__ X,
                                             __half* __restrict__ img, int K)
{
    const int kq = K >> 2;
    const int n = idx / kq, k = (idx - n * kq) << 2;
    const float4 v = *(const float4*)(X + (size_t)n * K + k);
    const int ntileK = K >> 5;
    *(__half2*)(img + bimg_off_h(n, k,     ntileK)) = __floats2half2_rn(v.x, v.y);
    *(__half2*)(img + bimg_off_h(n, k + 2, ntileK)) = __floats2half2_rn(v.z, v.w);
}

// ---------------------------------------------------------------------------
// Fused prologue: RoPE table + all operand image transforms in one launch.
// ---------------------------------------------------------------------------
__global__ void prologue(const float* __restrict__ hidden,
                         const float* __restrict__ wqkv,
                         const float* __restrict__ wo,
                         const int*   __restrict__ pos_ids)
{
    const int bid = blockIdx.x;
    if (bid < 512) {
        const int idx = bid * 256 + threadIdx.x;          // NTOK*32
        const int bs = idx >> 5;
        const int d  = idx & 31;
        const float FCOEF = -0.41524101186091903f;
        const float pos = (float)pos_ids[bs];
        const float f = pos * exp2f((float)d * FCOEF);
        float sn, cs;
        sincosf(f, &sn, &cs);
        g_rope[(size_t)bs * 64 + d]      = cs;
        g_rope[(size_t)bs * 64 + 32 + d] = sn;
    } else if (bid < 3584) {
        xform_a_body((bid - 512) * 256 + threadIdx.x, hidden, g_hidH, DD);
    } else if (bid < 5312) {
        xform_b_body((bid - 3584) * 256 + threadIdx.x, wqkv, g_wqH, DD);
    } else {
        xform_b_body((bid - 5312) * 256 + threadIdx.x, wo, g_woH, DD);
    }
}

// ---------------------------------------------------------------------------
// fp16 GEMM on tile images (unchanged).
// ---------------------------------------------------------------------------
#define GEMM_SMEM 65536   // 4 stages x (8KB A + 8KB B)

__global__ __launch_bounds__(256, 2) void gemm_h(const __half* __restrict__ Aimg,
                                                 const __half* __restrict__ Bimg,
                                                 float* __restrict__ C,
                                                 int N, int ntileK)
{
    extern __shared__ __half smh[];
    const uint32_t sbase = smem_u32(smh);
    const int tid    = threadIdx.x;
    const int wid    = tid >> 5;
    const int lane   = tid & 31;
    const int mt     = blockIdx.y;
    const int nt     = blockIdx.x;
    const int warp_m = wid >> 2;
    const int warp_n = wid & 3;

    float acc[4][4][4];
#pragma unroll
    for (int a = 0; a < 4; a++)
#pragma unroll
        for (int b = 0; b < 4; b++)
#pragma unroll
            for (int r = 0; r < 4; r++) acc[a][b][r] = 0.f;

    const int nch = ntileK;
    const __half* Atile0 = Aimg + ((size_t)(mt * ntileK) << 12) + (tid << 3);
    const __half* Btile0 = Bimg + ((size_t)(nt * ntileK) << 12) + (tid << 3);

#define ISSUE(c) do {                                                     \
    if ((c) < nch) {                                                      \
        const __half* As_ = Atile0 + ((size_t)(c) << 12);                 \
        const __half* Bs_ = Btile0 + ((size_t)(c) << 12);                 \
        uint32_t sa_ = sbase + ((c) & 3) * 16384u + (tid << 4);           \
        CP_ASYNC16(sa_,          As_);                                    \
        CP_ASYNC16(sa_ + 4096u,  As_ + 2048);                             \
        CP_ASYNC16(sa_ + 8192u,  Bs_);                                    \
        CP_ASYNC16(sa_ + 12288u, Bs_ + 2048);                             \
    }                                                                     \
    CP_COMMIT();                                                          \
} while (0)

    ISSUE(0); ISSUE(1); ISSUE(2); ISSUE(3);

    const int afo = warp_m * 2048 + lane * 8;
    const int bfo = 4096 + warp_n * 1024 + lane * 8;

    for (int c = 0; c < nch; c++) {
        CP_WAIT3();
        __syncthreads();

        const __half* s = smh + (c & 3) * 8192;
#pragma unroll
        for (int ki = 0; ki < 2; ki++) {
            uint32_t af[4][4], bf[4][2];
#pragma unroll
            for (int a = 0; a < 4; a++) {
                uint4 v = *(const uint4*)(s + afo + a * 512 + ki * 256);
                af[a][0] = v.x; af[a][1] = v.y; af[a][2] = v.z; af[a][3] = v.w;
            }
#pragma unroll
            for (int t = 0; t < 2; t++) {
                uint4 v = *(const uint4*)(s + bfo + t * 512 + ki * 256);
                bf[2*t][0]   = v.x; bf[2*t][1]   = v.y;
                bf[2*t+1][0] = v.z; bf[2*t+1][1] = v.w;
            }
#pragma unroll
            for (int a = 0; a < 4; a++)
#pragma unroll
                for (int b = 0; b < 4; b++)
                    mma_f16(acc[a][b], af[a], bf[b]);
        }
        __syncthreads();
        ISSUE(c + 4);
    }

    const int g = lane >> 2, u = lane & 3;
#pragma unroll
    for (int a = 0; a < 4; a++) {
        const int row = mt * 128 + warp_m * 64 + a * 16 + g;
#pragma unroll
        for (int b = 0; b < 4; b++) {
            const int col = nt * 128 + warp_n * 32 + b * 8 + 2 * u;
            *(float2*)(C + (size_t)row * N + col)       = make_float2(acc[a][b][0], acc[a][b][1]);
            *(float2*)(C + (size_t)(row + 8) * N + col) = make_float2(acc[a][b][2], acc[a][b][3]);
        }
    }
#undef ISSUE
}

// ---------------------------------------------------------------------------
// Fused RoPE (table) + sliding-window attention, fp16 m16n8k16 + ldmatrix.
// Output written DIRECTLY as fp16 A-image tiles (smem-staged, coalesced).
// ---------------------------------------------------------------------------
#define KPH 72
#define VHP 72
#define QPH 72
#define VH_OFF (256 * KPH)            // 18432 halves
#define QH_OFF (VH_OFF + 256 * VHP)   // 36864 halves
#define ATTN_SMEM ((QH_OFF + 128 * QPH) * 2)   // 92160 bytes

__device__ __forceinline__ void rope4t(float4 cs, float4 sn, float4 x, float4 y,
                                       float4& lo, float4& hi)
{
    lo.x = x.x * cs.x - y.x * sn.x;  hi.x = y.x * cs.x + x.x * sn.x;
    lo.y = x.y * cs.y - y.y * sn.y;  hi.y = y.y * cs.y + x.y * sn.y;
    lo.z = x.z * cs.z - y.z * sn.z;  hi.z = y.z * cs.z + x.z * sn.z;
    lo.w = x.w * cs.w - y.w * sn.w;  hi.w = y.w * cs.w + x.w * sn.w;
}

__global__ __launch_bounds__(256, 2) void attn_mma()
{
    extern __shared__ __half smha[];
    __half* Kh = smha;
    __half* Vh = smha + VH_OFF;
    __half* Qh = smha + QH_OFF;

    const int tid  = threadIdx.x;
    const int lane = tid & 31;
    const int w    = tid >> 5;
    const int g    = lane >> 2;
    const int t    = lane & 3;
    const int j    = lane >> 3;      // ldmatrix matrix index
    const int rim  = lane & 7;       // ldmatrix row-in-matrix
    const int qb   = blockIdx.x;
    const int bh   = blockIdx.y;
    const int b    = bh / HH;
    const int h    = bh % HH;
    const int kstart = qb * 128 - 64;

    // ---- Phase A: stage K (RoPE->fp16), V (fp16 row-major), Q (RoPE,scaled) ----
    {
        const int r  = tid;
        const int kg = kstart + r;
        __half* kd = Kh + r * KPH;
        __half* vd = Vh + r * VHP;
        if (kg >= 0 && kg < SS) {
            const float* kp = g_qkv + ((size_t)(b * SS + kg)) * QKVD + DD + h * HDIM;
            const float* vp = kp + DD;
            const float* rp = g_rope + ((size_t)(b * SS + kg)) * 64;
            __half2 hbuf[32];
#pragma unroll
            for (int i = 0; i < 8; i++) {
                float4 x  = ((const float4*)kp)[i];
                float4 y  = ((const float4*)kp)[i + 8];
                float4 cs = ((const float4*)rp)[i];
                float4 sn = ((const float4*)rp)[i + 8];
                float4 lo, hi;
                rope4t(cs, sn, x, y, lo, hi);
                hbuf[i * 2]      = __floats2half2_rn(lo.x, lo.y);
                hbuf[i * 2 + 1]  = __floats2half2_rn(lo.z, lo.w);
                hbuf[16 + i * 2] = __floats2half2_rn(hi.x, hi.y);
                hbuf[17 + i * 2] = __floats2half2_rn(hi.z, hi.w);
            }
#pragma unroll
            for (int q = 0; q < 8; q++)
                ((uint4*)kd)[q] = ((const uint4*)hbuf)[q];
            __half2 vbuf[32];
#pragma unroll
            for (int i = 0; i < 16; i++) {
                float4 v = ((const float4*)vp)[i];
                vbuf[2 * i]     = __floats2half2_rn(v.x, v.y);
                vbuf[2 * i + 1] = __floats2half2_rn(v.z, v.w);
            }
#pragma unroll
            for (int q = 0; q < 8; q++)
                ((uint4*)vd)[q] = ((const uint4*)vbuf)[q];
        } else {
            const uint4 z = make_uint4(0, 0, 0, 0);
#pragma unroll
            for (int q = 0; q < 8; q++) {
                ((uint4*)kd)[q] = z;
                ((uint4*)vd)[q] = z;
            }
        }
        if (tid < 128) {
            const int qg = qb * 128 + tid;
            const float* qp = g_qkv + ((size_t)(b * SS + qg)) * QKVD + h * HDIM;
            const float* rp = g_rope + ((size_t)(b * SS + qg)) * 64;
            __half* qd = Qh + tid * QPH;
            const float QSC = 0.125f * 1.4426950408889634f;  // scale * log2(e)
            __half2 hbuf[32];
#pragma unroll
            for (int i = 0; i < 8; i++) {
                float4 x  = ((const float4*)qp)[i];
                float4 y  = ((const float4*)qp)[i + 8];
                float4 cs = ((const float4*)rp)[i];
                float4 sn = ((const float4*)rp)[i + 8];
                float4 lo, hi;
                rope4t(cs, sn, x, y, lo, hi);
                hbuf[i * 2]      = __floats2half2_rn(lo.x * QSC, lo.y * QSC);
                hbuf[i * 2 + 1]  = __floats2half2_rn(lo.z * QSC, lo.w * QSC);
                hbuf[16 + i * 2] = __floats2half2_rn(hi.x * QSC, hi.y * QSC);
                hbuf[17 + i * 2] = __floats2half2_rn(hi.z * QSC, hi.w * QSC);
            }
#pragma unroll
            for (int q = 0; q < 8; q++)
                ((uint4*)qd)[q] = ((const uint4*)hbuf)[q];
        }
    }
    __syncthreads();

    const uint32_t kh_base = smem_u32(Kh);
    const uint32_t vh_base = smem_u32(Vh);
    const uint32_t qh_base = smem_u32(Qh);
    const uint32_t pw_base = qh_base + (uint32_t)((w << 4) * QPH * 2);

    // ---- Q A-fragments via ldmatrix.x4 ----
    const int rl = (w << 4) + g;            // low local q-row of this lane
    uint32_t aq[4][4];
    {
        const uint32_t qa = qh_base +
            (uint32_t)((((w << 4) + rim + 8 * (j & 1)) * QPH + 8 * (j >> 1)) * 2);
#pragma unroll
        for (int s = 0; s < 4; s++)
            LDSM_X4(aq[s][0], aq[s][1], aq[s][2], aq[s][3], qa + 32u * s);
    }
    __syncwarp();

    float m0 = -1e4f, m1 = -1e4f, l0 = 0.f, l1 = 0.f;
    float oacc[8][4];
#pragma unroll
    for (int d = 0; d < 8; d++)
#pragma unroll
        for (int r = 0; r < 4; r++) oacc[d][r] = 0.f;

    __half* Pw = Qh + (w << 4) * QPH;
    const int cw = (w >= 4) ? 1 : 0;

    const uint32_t k_lds0 = kh_base + (uint32_t)(((8 * (j >> 1) + rim) * KPH + 8 * (j & 1)) * 2);
    const uint32_t v_lds0 = vh_base + (uint32_t)(((8 * (j & 1) + rim) * VHP + 8 * (j >> 1)) * 2);
    const uint32_t p_lds0 = pw_base + (uint32_t)(((rim + 8 * (j & 1)) * QPH + 8 * (j >> 1)) * 2);

    for (int ci = 0; ci < 3; ci++) {
        const int kbase = (cw + ci) * 64;

        // ---- S = Q @ K^T ----
        float sacc[8][4];
#pragma unroll
        for (int q = 0; q < 8; q++)
#pragma unroll
            for (int r = 0; r < 4; r++) sacc[q][r] = 0.f;

#pragma unroll
        for (int s = 0; s < 4; s++) {
#pragma unroll
            for (int jp = 0; jp < 4; jp++) {
                uint32_t r0, r1, r2, r3;
                const uint32_t ka = k_lds0 +
                    (uint32_t)((kbase + 16 * jp) * KPH * 2) + 32u * s;
                LDSM_X4(r0, r1, r2, r3, ka);
                uint32_t b0[2] = {r0, r1};
                uint32_t b1[2] = {r2, r3};
                mma_f16(sacc[2 * jp],     aq[s], b0);
                mma_f16(sacc[2 * jp + 1], aq[s], b1);
            }
        }

        // ---- mask + per-row chunk max ----
        float mx0 = -30000.f, mx1 = -30000.f;
#pragma unroll
        for (int jt = 0; jt < 8; jt++) {
            const int k0 = kbase + 8 * jt + 2 * t;
            const int k1 = k0 + 1;
            const int kg0 = kstart + k0, kg1 = kstart + k1;
            const bool in0 = (kg0 >= 0) & (kg0 < SS);
            const bool in1 = (kg1 >= 0) & (kg1 < SS);
            const bool v00 = in0 && ((unsigned)(k0 - rl) <= 128u);
            const bool v01 = in1 && ((unsigned)(k1 - rl) <= 128u);
            const bool v10 = in0 && ((unsigned)(k0 - rl - 8) <= 128u);
            const bool v11 = in1 && ((unsigned)(k1 - rl - 8) <= 128u);
            sacc[jt][0] = v00 ? sacc[jt][0] : -30000.f;
            sacc[jt][1] = v01 ? sacc[jt][1] : -30000.f;
            sacc[jt][2] = v10 ? sacc[jt][2] : -30000.f;
            sacc[jt][3] = v11 ? sacc[jt][3] : -30000.f;
            mx0 = fmaxf(mx0, fmaxf(sacc[jt][0], sacc[jt][1]));
            mx1 = fmaxf(mx1, fmaxf(sacc[jt][2], sacc[jt][3]));
        }
        mx0 = fmaxf(mx0, __shfl_xor_sync(0xffffffff, mx0, 1));
        mx0 = fmaxf(mx0, __shfl_xor_sync(0xffffffff, mx0, 2));
        mx1 = fmaxf(mx1, __shfl_xor_sync(0xffffffff, mx1, 1));
        mx1 = fmaxf(mx1, __shfl_xor_sync(0xffffffff, mx1, 2));

        const float m0n = fmaxf(m0, mx0);
        const float m1n = fmaxf(m1, mx1);
        const float a0 = exp2f(m0 - m0n);
        const float a1 = exp2f(m1 - m1n);
        m0 = m0n; m1 = m1n;
        l0 *= a0; l1 *= a1;
#pragma unroll
        for (int d = 0; d < 8; d++) {
            oacc[d][0] *= a0; oacc[d][1] *= a0;
            oacc[d][2] *= a1; oacc[d][3] *= a1;
        }

        // ---- p = exp2(s - m), fp16-rounded; store to Pw; row-sums ----
        float rs0 = 0.f, rs1 = 0.f;
#pragma unroll
        for (int jt = 0; jt < 8; jt++) {
            __half2 hp0 = __floats2half2_rn(exp2f(sacc[jt][0] - m0),
                                            exp2f(sacc[jt][1] - m0));
            __half2 hp1 = __floats2half2_rn(exp2f(sacc[jt][2] - m1),
                                            exp2f(sacc[jt][3] - m1));
            float2 f0 = __half22float2(hp0);
            float2 f1 = __half22float2(hp1);
            rs0 += f0.x + f0.y;
            rs1 += f1.x + f1.y;
            const int pc = 8 * jt + 2 * t;
            *(__half2*)(Pw + g * QPH + pc)       = hp0;
            *(__half2*)(Pw + (g + 8) * QPH + pc) = hp1;
        }
        rs0 += __shfl_xor_sync(0xffffffff, rs0, 1);
        rs0 += __shfl_xor_sync(0xffffffff, rs0, 2);
        rs1 += __shfl_xor_sync(0xffffffff, rs1, 1);
        rs1 += __shfl_xor_sync(0xffffffff, rs1, 2);
        l0 += rs0; l1 += rs1;
        __syncwarp();

        // ---- O += P @ V ----
#pragma unroll
        for (int s = 0; s < 4; s++) {
            uint32_t pa[4];
            LDSM_X4(pa[0], pa[1], pa[2], pa[3], p_lds0 + 32u * s);
#pragma unroll
            for (int dp = 0; dp < 4; dp++) {
                uint32_t r0, r1, r2, r3;
                const uint32_t va = v_lds0 +
                    (uint32_t)((kbase + 16 * s) * VHP * 2) + 32u * dp;
                LDSM_X4T(r0, r1, r2, r3, va);
                uint32_t b0[2] = {r0, r1};
                uint32_t b1[2] = {r2, r3};
                mma_f16(oacc[2 * dp],     pa, b0);
                mma_f16(oacc[2 * dp + 1], pa, b1);
            }
        }
        __syncwarp();
    }

    // ---- normalize + emit DIRECTLY as two fp16 A-image tiles ----
    __syncthreads();                     // all warps done reading Kh/Vh
    __half* stage = Kh;                  // 16 KB staging: tiles kc=0,1
    const float inv0 = 1.f / l0;
    const float inv1 = 1.f / l1;
#pragma unroll
    for (int u = 0; u < 4; u++) {
        // dt pair (2u, 2u+1): tile u>>1, subtile w*2 + (u&1), slot = lane
        __half2 e01 = __floats2half2_rn(oacc[2*u][0]   * inv0, oacc[2*u][1]   * inv0);
        __half2 e23 = __floats2half2_rn(oacc[2*u][2]   * inv1, oacc[2*u][3]   * inv1);
        __half2 e45 = __floats2half2_rn(oacc[2*u+1][0] * inv0, oacc[2*u+1][1] * inv0);
        __half2 e67 = __floats2half2_rn(oacc[2*u+1][2] * inv1, oacc[2*u+1][3] * inv1);
        uint4 pack;
        pack.x = *(uint32_t*)&e01;
        pack.y = *(uint32_t*)&e23;
        pack.z = *(uint32_t*)&e45;
        pack.w = *(uint32_t*)&e67;
        __half* dst = stage + ((u >> 1) << 12) + (((w << 1) + (u & 1)) << 8) + (lane << 3);
        *(uint4*)dst = pack;
    }
    __syncthreads();

    // cooperative coalesced copy of both 8 KB tiles to g_attnH
    {
        const int mt = (b * SS + qb * 128) >> 7;         // row tile
        const int kc0 = h * 2;                           // first of 2 k-chunks
        __half* gdst = g_attnH + ((size_t)(mt * (DD / 32) + kc0) << 12);
        const uint4* src = (const uint4*)stage;
        uint4* dst = (uint4*)gdst;
        // 2 tiles x 4096 halves = 1024 uint4; 256 threads x 4 each
#pragma unroll
        for (int i = 0; i < 4; i++)
            dst[tid + 256 * i] = src[tid + 256 * i];
    }
}

// ---------------------------------------------------------------------------
extern "C" void kernel_launch(void* const* d_in, const int* in_sizes, int n_in,
                              void* d_out, int out_size)
{
    const float* hidden = (const float*)d_in[0];
    const float* wqkv   = (const float*)d_in[1];
    const float* wo     = (const float*)d_in[2];
    const int*   pos    = (const int*)d_in[4];
    float*       out    = (float*)d_out;

    float  *qkv_p;
    __half *hidH_p, *attnH_p, *wqH_p, *woH_p;
    cudaGetSymbolAddress((void**)&qkv_p,   g_qkv);
    cudaGetSymbolAddress((void**)&hidH_p,  g_hidH);
    cudaGetSymbolAddress((void**)&attnH_p, g_attnH);
    cudaGetSymbolAddress((void**)&wqH_p,   g_wqH);
    cudaGetSymbolAddress((void**)&woH_p,   g_woH);

    cudaFuncSetAttribute(gemm_h,   cudaFuncAttributeMaxDynamicSharedMemorySize, GEMM_SMEM);
    cudaFuncSetAttribute(attn_mma, cudaFuncAttributeMaxDynamicSharedMemorySize, ATTN_SMEM);

    // 0) fused prologue: RoPE table + all operand images (one launch)
    prologue<<<5888, 256>>>(hidden, wqkv, wo, pos);

    // 1) QKV = hidden @ Wqkv^T   [4096, 2304] row-major fp32
    gemm_h<<<dim3(QKVD / 128, NTOK / 128), 256, GEMM_SMEM>>>(hidH_p, wqH_p, qkv_p,
                                                             QKVD, DD / 32);
    // 2) fused RoPE + sliding-window attention -> g_attnH (fp16 A-image, direct)
    attn_mma<<<dim3(SS / 128, BB * HH), 256, ATTN_SMEM>>>();
    // 3) out = attn @ Wo^T       [4096, 768] row-major fp32
    gemm_h<<<dim3(DD / 128, NTOK / 128), 256, GEMM_SMEM>>>(attnH_p, woH_p, out,
                                                           DD, DD / 32);
}

// round 12
// speedup vs baseline: 2.0328x; 1.1733x over previous
#include <cuda_runtime.h>
#include <cuda_fp16.h>
#include <math.h>
#include <stdint.h>

// Problem constants
#define BB   2
#define SS   2048
#define DD   768
#define HH   12
#define HDIM 64
#define QKVD 2304           // 3*D per token
#define NTOK (BB*SS)        // 4096

// Scratch (allocation-free rule: __device__ globals)
__device__ float  g_qkv[(size_t)NTOK * QKVD];   // [4096, 2304] row-major fp32
__device__ float  g_rope[(size_t)NTOK * 64];    // [token][cos32|sin32]
__device__ __half g_hidH[(size_t)NTOK * DD];    // hidden as A-image (fp16)
__device__ __half g_attnH[(size_t)NTOK * DD];   // attn out as A-image (fp16)
__device__ __half g_wqH[(size_t)QKVD * DD];     // Wqkv as B-image (fp16)
__device__ __half g_woH[(size_t)DD * DD];       // Wo as B-image (fp16)

__device__ __forceinline__ uint32_t smem_u32(const void* p) {
    uint32_t a;
    asm("{ .reg .u64 t; cvta.to.shared.u64 t, %1; cvt.u32.u64 %0, t; }"
        : "=r"(a) : "l"(p));
    return a;
}

__device__ __forceinline__ void mma_f16(float c[4], const uint32_t a[4], const uint32_t b[2]) {
    asm volatile(
        "mma.sync.aligned.m16n8k16.row.col.f32.f16.f16.f32 "
        "{%0,%1,%2,%3}, {%4,%5,%6,%7}, {%8,%9}, {%0,%1,%2,%3};"
        : "+f"(c[0]), "+f"(c[1]), "+f"(c[2]), "+f"(c[3])
        : "r"(a[0]), "r"(a[1]), "r"(a[2]), "r"(a[3]), "r"(b[0]), "r"(b[1]));
}

#define LDSM_X4(r0,r1,r2,r3,a) \
    asm volatile("ldmatrix.sync.aligned.m8n8.x4.shared.b16 {%0,%1,%2,%3}, [%4];" \
                 : "=r"(r0), "=r"(r1), "=r"(r2), "=r"(r3) : "r"(a))
#define LDSM_X4T(r0,r1,r2,r3,a) \
    asm volatile("ldmatrix.sync.aligned.m8n8.x4.trans.shared.b16 {%0,%1,%2,%3}, [%4];" \
                 : "=r"(r0), "=r"(r1), "=r"(r2), "=r"(r3) : "r"(a))

#define CP_ASYNC16(dst, src) \
    asm volatile("cp.async.cg.shared.global [%0], [%1], 16;" :: "r"(dst), "l"(src))
#define CP_COMMIT() asm volatile("cp.async.commit_group;" ::: "memory")
#define CP_WAIT2()  asm volatile("cp.async.wait_group 2;"  ::: "memory")

// ---------------------------------------------------------------------------
// fp16 tile-image layouts. Tile: 128 rows x 32 k-cols = 4096 halves (8 KB).
// ---------------------------------------------------------------------------
__device__ __forceinline__ size_t aimg_off_h(int r, int k, int ntileK) {
    const int mt = r >> 7, kc = k >> 5;
    const int mi = (r >> 4) & 7, rr = r & 15;
    const int ki = (k >> 4) & 1, kk = k & 15;
    const int lane = ((rr & 7) << 2) + ((kk & 7) >> 1);
    const int e = (kk & 1) + ((rr >> 3) << 1) + ((kk >> 3) << 2);
    return ((size_t)(mt * ntileK + kc) << 12) + (((mi << 1) + ki) << 8) + (lane << 3) + e;
}
__device__ __forceinline__ size_t bimg_off_h(int n, int k, int ntileK) {
    const int nt = n >> 7, kc = k >> 5;
    const int pr = (n >> 4) & 7, p = (n >> 3) & 1, nn = n & 7;
    const int ki = (k >> 4) & 1, kk = k & 15;
    const int lane = (nn << 2) + ((kk & 7) >> 1);
    const int e = (kk & 1) + ((kk >> 3) << 1) + (p << 2);
    return ((size_t)(nt * ntileK + kc) << 12) + (((pr << 1) + ki) << 8) + (lane << 3) + e;
}

__device__ __forceinline__ void xform_a_body(int idx, const float* __restrict__ X,
                                             __half* __restrict__ img, int K)
{
    const int kq = K >> 2;
    const int r = idx / kq, k = (idx - r * kq) << 2;
    const float4 v = *(const float4*)(X + (size_t)r * K + k);
    const int ntileK = K >> 5;
    *(__half2*)(img + aimg_off_h(r, k,     ntileK)) = __floats2half2_rn(v.x, v.y);
    *(__half2*)(img + aimg_off_h(r, k + 2, ntileK)) = __floats2half2_rn(v.z, v.w);
}

__device__ __forceinline__ void xform_b_body(int idx, const float* __restrict__ X,
                                             __half* __restrict__ img, int K)
{
    const int kq = K >> 2;
    const int n = idx / kq, k = (idx - n * kq) << 2;
    const float4 v = *(const float4*)(X + (size_t)n * K + k);
    const int ntileK = K >> 5;
    *(__half2*)(img + bimg_off_h(n, k,     ntileK)) = __floats2half2_rn(v.x, v.y);
    *(__half2*)(img + bimg_off_h(n, k + 2, ntileK)) = __floats2half2_rn(v.z, v.w);
}

// ---------------------------------------------------------------------------
// Fused prologue: RoPE table + all operand image transforms in one launch.
// ---------------------------------------------------------------------------
__global__ void prologue(const float* __restrict__ hidden,
                         const float* __restrict__ wqkv,
                         const float* __restrict__ wo,
                         const int*   __restrict__ pos_ids)
{
    const int bid = blockIdx.x;
    if (bid < 512) {
        const int idx = bid * 256 + threadIdx.x;          // NTOK*32
        const int bs = idx >> 5;
        const int d  = idx & 31;
        const float FCOEF = -0.41524101186091903f;
        const float pos = (float)pos_ids[bs];
        const float f = pos * exp2f((float)d * FCOEF);
        float sn, cs;
        sincosf(f, &sn, &cs);
        g_rope[(size_t)bs * 64 + d]      = cs;
        g_rope[(size_t)bs * 64 + 32 + d] = sn;
    } else if (bid < 3584) {
        xform_a_body((bid - 512) * 256 + threadIdx.x, hidden, g_hidH, DD);
    } else if (bid < 5312) {
        xform_b_body((bid - 3584) * 256 + threadIdx.x, wqkv, g_wqH, DD);
    } else {
        xform_b_body((bid - 5312) * 256 + threadIdx.x, wo, g_woH, DD);
    }
}

// ---------------------------------------------------------------------------
// fp16 GEMM on tile images. 4-buffer ring, 3-deep prefetch, ONE sync/chunk.
// ---------------------------------------------------------------------------
#define GEMM_SMEM 65536   // 4 buffers x (8KB A + 8KB B)

__global__ __launch_bounds__(256, 2) void gemm_h(const __half* __restrict__ Aimg,
                                                 const __half* __restrict__ Bimg,
                                                 float* __restrict__ C,
                                                 int N, int ntileK)
{
    extern __shared__ __half smh[];
    const uint32_t sbase = smem_u32(smh);
    const int tid    = threadIdx.x;
    const int wid    = tid >> 5;
    const int lane   = tid & 31;
    const int mt     = blockIdx.y;
    const int nt     = blockIdx.x;
    const int warp_m = wid >> 2;
    const int warp_n = wid & 3;

    float acc[4][4][4];
#pragma unroll
    for (int a = 0; a < 4; a++)
#pragma unroll
        for (int b = 0; b < 4; b++)
#pragma unroll
            for (int r = 0; r < 4; r++) acc[a][b][r] = 0.f;

    const int nch = ntileK;
    const __half* Atile0 = Aimg + ((size_t)(mt * ntileK) << 12) + (tid << 3);
    const __half* Btile0 = Bimg + ((size_t)(nt * ntileK) << 12) + (tid << 3);

#define ISSUE(c) do {                                                     \
    if ((c) < nch) {                                                      \
        const __half* As_ = Atile0 + ((size_t)(c) << 12);                 \
        const __half* Bs_ = Btile0 + ((size_t)(c) << 12);                 \
        uint32_t sa_ = sbase + ((c) & 3) * 16384u + (tid << 4);           \
        CP_ASYNC16(sa_,          As_);                                    \
        CP_ASYNC16(sa_ + 4096u,  As_ + 2048);                             \
        CP_ASYNC16(sa_ + 8192u,  Bs_);                                    \
        CP_ASYNC16(sa_ + 12288u, Bs_ + 2048);                             \
    }                                                                     \
    CP_COMMIT();                                                          \
} while (0)

    ISSUE(0); ISSUE(1); ISSUE(2);

    const int afo = warp_m * 2048 + lane * 8;
    const int bfo = 4096 + warp_n * 1024 + lane * 8;

    for (int c = 0; c < nch; c++) {
        CP_WAIT2();
        __syncthreads();

        const __half* s = smh + (c & 3) * 8192;
#pragma unroll
        for (int ki = 0; ki < 2; ki++) {
            uint32_t af[4][4], bf[4][2];
#pragma unroll
            for (int a = 0; a < 4; a++) {
                uint4 v = *(const uint4*)(s + afo + a * 512 + ki * 256);
                af[a][0] = v.x; af[a][1] = v.y; af[a][2] = v.z; af[a][3] = v.w;
            }
#pragma unroll
            for (int t = 0; t < 2; t++) {
                uint4 v = *(const uint4*)(s + bfo + t * 512 + ki * 256);
                bf[2*t][0]   = v.x; bf[2*t][1]   = v.y;
                bf[2*t+1][0] = v.z; bf[2*t+1][1] = v.w;
            }
#pragma unroll
            for (int a = 0; a < 4; a++)
#pragma unroll
                for (int b = 0; b < 4; b++)
                    mma_f16(acc[a][b], af[a], bf[b]);
        }
        // writes buffer (c+3)&3 == (c-1)&3: everyone finished reading it
        // before this iteration's __syncthreads.
        ISSUE(c + 3);
    }

    const int g = lane >> 2, u = lane & 3;
#pragma unroll
    for (int a = 0; a < 4; a++) {
        const int row = mt * 128 + warp_m * 64 + a * 16 + g;
#pragma unroll
        for (int b = 0; b < 4; b++) {
            const int col = nt * 128 + warp_n * 32 + b * 8 + 2 * u;
            *(float2*)(C + (size_t)row * N + col)       = make_float2(acc[a][b][0], acc[a][b][1]);
            *(float2*)(C + (size_t)(row + 8) * N + col) = make_float2(acc[a][b][2], acc[a][b][3]);
        }
    }
#undef ISSUE
}

// ---------------------------------------------------------------------------
// Fused RoPE (table) + sliding-window attention, fp16 m16n8k16 + ldmatrix.
// Phase A coalesced: 8 threads per row. Output direct fp16 A-image tiles.
// ---------------------------------------------------------------------------
#define KPH 72
#define VHP 72
#define QPH 72
#define VH_OFF (256 * KPH)            // 18432 halves
#define QH_OFF (VH_OFF + 256 * VHP)   // 36864 halves
#define ATTN_SMEM ((QH_OFF + 128 * QPH) * 2)   // 92160 bytes

__device__ __forceinline__ void rope4t(float4 cs, float4 sn, float4 x, float4 y,
                                       float4& lo, float4& hi)
{
    lo.x = x.x * cs.x - y.x * sn.x;  hi.x = y.x * cs.x + x.x * sn.x;
    lo.y = x.y * cs.y - y.y * sn.y;  hi.y = y.y * cs.y + x.y * sn.y;
    lo.z = x.z * cs.z - y.z * sn.z;  hi.z = y.z * cs.z + x.z * sn.z;
    lo.w = x.w * cs.w - y.w * sn.w;  hi.w = y.w * cs.w + x.w * sn.w;
}

__device__ __forceinline__ uint32_t h4(float4 v) {
    // pack 4 floats -> 4 halves (returned as 2x half2 in a uint2-like pair)
    __half2 a = __floats2half2_rn(v.x, v.y);
    return *(uint32_t*)&a;
}

__global__ __launch_bounds__(256, 2) void attn_mma()
{
    extern __shared__ __half smha[];
    __half* Kh = smha;
    __half* Vh = smha + VH_OFF;
    __half* Qh = smha + QH_OFF;

    const int tid  = threadIdx.x;
    const int lane = tid & 31;
    const int w    = tid >> 5;
    const int g    = lane >> 2;
    const int t    = lane & 3;
    const int j    = lane >> 3;      // ldmatrix matrix index
    const int rim  = lane & 7;       // ldmatrix row-in-matrix
    const int qb   = blockIdx.x;
    const int bh   = blockIdx.y;
    const int b    = bh / HH;
    const int h    = bh % HH;
    const int kstart = qb * 128 - 64;

    // ---- Phase A (coalesced): 8 threads per row; thread handles float4 c8
    //      (dims 4c8..4c8+3) and c8+8 (dims +32) = one RoPE pair group. ----
    {
        const int rg8 = tid >> 3;        // row group 0..31
        const int c8  = tid & 7;         // float4 slot within row
#pragma unroll
        for (int i = 0; i < 8; i++) {
            const int r  = rg8 + 32 * i;          // 0..255
            const int kg = kstart + r;
            __half* kd = Kh + r * KPH;
            __half* vd = Vh + r * VHP;
            if (kg >= 0 && kg < SS) {
                const float* kp = g_qkv + ((size_t)(b * SS + kg)) * QKVD + DD + h * HDIM;
                const float* vp = kp + DD;
                const float* rp = g_rope + ((size_t)(b * SS + kg)) * 64;
                float4 x  = ((const float4*)kp)[c8];
                float4 y  = ((const float4*)kp)[c8 + 8];
                float4 cs = ((const float4*)rp)[c8];
                float4 sn = ((const float4*)rp)[c8 + 8];
                float4 lo, hi;
                rope4t(cs, sn, x, y, lo, hi);
                __half2 l01 = __floats2half2_rn(lo.x, lo.y);
                __half2 l23 = __floats2half2_rn(lo.z, lo.w);
                __half2 h01 = __floats2half2_rn(hi.x, hi.y);
                __half2 h23 = __floats2half2_rn(hi.z, hi.w);
                *(__half2*)(kd + c8 * 4)          = l01;
                *(__half2*)(kd + c8 * 4 + 2)      = l23;
                *(__half2*)(kd + 32 + c8 * 4)     = h01;
                *(__half2*)(kd + 32 + c8 * 4 + 2) = h23;
                float4 v0 = ((const float4*)vp)[c8];
                float4 v1 = ((const float4*)vp)[c8 + 8];
                *(__half2*)(vd + c8 * 4)          = __floats2half2_rn(v0.x, v0.y);
                *(__half2*)(vd + c8 * 4 + 2)      = __floats2half2_rn(v0.z, v0.w);
                *(__half2*)(vd + 32 + c8 * 4)     = __floats2half2_rn(v1.x, v1.y);
                *(__half2*)(vd + 32 + c8 * 4 + 2) = __floats2half2_rn(v1.z, v1.w);
            } else {
                const __half2 z = __floats2half2_rn(0.f, 0.f);
                *(__half2*)(kd + c8 * 4)          = z;
                *(__half2*)(kd + c8 * 4 + 2)      = z;
                *(__half2*)(kd + 32 + c8 * 4)     = z;
                *(__half2*)(kd + 32 + c8 * 4 + 2) = z;
                *(__half2*)(vd + c8 * 4)          = z;
                *(__half2*)(vd + c8 * 4 + 2)      = z;
                *(__half2*)(vd + 32 + c8 * 4)     = z;
                *(__half2*)(vd + 32 + c8 * 4 + 2) = z;
            }
        }
        const float QSC = 0.125f * 1.4426950408889634f;  // scale * log2(e)
#pragma unroll
        for (int i = 0; i < 4; i++) {
            const int r  = rg8 + 32 * i;          // 0..127
            const int qg = qb * 128 + r;
            const float* qp = g_qkv + ((size_t)(b * SS + qg)) * QKVD + h * HDIM;
            const float* rp = g_rope + ((size_t)(b * SS + qg)) * 64;
            __half* qd = Qh + r * QPH;
            float4 x  = ((const float4*)qp)[c8];
            float4 y  = ((const float4*)qp)[c8 + 8];
            float4 cs = ((const float4*)rp)[c8];
            float4 sn = ((const float4*)rp)[c8 + 8];
            float4 lo, hi;
            rope4t(cs, sn, x, y, lo, hi);
            lo.x *= QSC; lo.y *= QSC; lo.z *= QSC; lo.w *= QSC;
            hi.x *= QSC; hi.y *= QSC; hi.z *= QSC; hi.w *= QSC;
            *(__half2*)(qd + c8 * 4)          = __floats2half2_rn(lo.x, lo.y);
            *(__half2*)(qd + c8 * 4 + 2)      = __floats2half2_rn(lo.z, lo.w);
            *(__half2*)(qd + 32 + c8 * 4)     = __floats2half2_rn(hi.x, hi.y);
            *(__half2*)(qd + 32 + c8 * 4 + 2) = __floats2half2_rn(hi.z, hi.w);
        }
    }
    __syncthreads();

    const uint32_t kh_base = smem_u32(Kh);
    const uint32_t vh_base = smem_u32(Vh);
    const uint32_t qh_base = smem_u32(Qh);
    const uint32_t pw_base = qh_base + (uint32_t)((w << 4) * QPH * 2);

    // ---- Q A-fragments via ldmatrix.x4 ----
    const int rl = (w << 4) + g;            // low local q-row of this lane
    uint32_t aq[4][4];
    {
        const uint32_t qa = qh_base +
            (uint32_t)((((w << 4) + rim + 8 * (j & 1)) * QPH + 8 * (j >> 1)) * 2);
#pragma unroll
        for (int s = 0; s < 4; s++)
            LDSM_X4(aq[s][0], aq[s][1], aq[s][2], aq[s][3], qa + 32u * s);
    }
    __syncwarp();

    float m0 = -1e4f, m1 = -1e4f, l0 = 0.f, l1 = 0.f;
    float oacc[8][4];
#pragma unroll
    for (int d = 0; d < 8; d++)
#pragma unroll
        for (int r = 0; r < 4; r++) oacc[d][r] = 0.f;

    __half* Pw = Qh + (w << 4) * QPH;
    const int cw = (w >= 4) ? 1 : 0;

    const uint32_t k_lds0 = kh_base + (uint32_t)(((8 * (j >> 1) + rim) * KPH + 8 * (j & 1)) * 2);
    const uint32_t v_lds0 = vh_base + (uint32_t)(((8 * (j & 1) + rim) * VHP + 8 * (j >> 1)) * 2);
    const uint32_t p_lds0 = pw_base + (uint32_t)(((rim + 8 * (j & 1)) * QPH + 8 * (j >> 1)) * 2);

    for (int ci = 0; ci < 3; ci++) {
        const int kbase = (cw + ci) * 64;

        // ---- S = Q @ K^T ----
        float sacc[8][4];
#pragma unroll
        for (int q = 0; q < 8; q++)
#pragma unroll
            for (int r = 0; r < 4; r++) sacc[q][r] = 0.f;

#pragma unroll
        for (int s = 0; s < 4; s++) {
#pragma unroll
            for (int jp = 0; jp < 4; jp++) {
                uint32_t r0, r1, r2, r3;
                const uint32_t ka = k_lds0 +
                    (uint32_t)((kbase + 16 * jp) * KPH * 2) + 32u * s;
                LDSM_X4(r0, r1, r2, r3, ka);
                uint32_t b0[2] = {r0, r1};
                uint32_t b1[2] = {r2, r3};
                mma_f16(sacc[2 * jp],     aq[s], b0);
                mma_f16(sacc[2 * jp + 1], aq[s], b1);
            }
        }

        // ---- mask + per-row chunk max ----
        float mx0 = -30000.f, mx1 = -30000.f;
#pragma unroll
        for (int jt = 0; jt < 8; jt++) {
            const int k0 = kbase + 8 * jt + 2 * t;
            const int k1 = k0 + 1;
            const int kg0 = kstart + k0, kg1 = kstart + k1;
            const bool in0 = (kg0 >= 0) & (kg0 < SS);
            const bool in1 = (kg1 >= 0) & (kg1 < SS);
            const bool v00 = in0 && ((unsigned)(k0 - rl) <= 128u);
            const bool v01 = in1 && ((unsigned)(k1 - rl) <= 128u);
            const bool v10 = in0 && ((unsigned)(k0 - rl - 8) <= 128u);
            const bool v11 = in1 && ((unsigned)(k1 - rl - 8) <= 128u);
            sacc[jt][0] = v00 ? sacc[jt][0] : -30000.f;
            sacc[jt][1] = v01 ? sacc[jt][1] : -30000.f;
            sacc[jt][2] = v10 ? sacc[jt][2] : -30000.f;
            sacc[jt][3] = v11 ? sacc[jt][3] : -30000.f;
            mx0 = fmaxf(mx0, fmaxf(sacc[jt][0], sacc[jt][1]));
            mx1 = fmaxf(mx1, fmaxf(sacc[jt][2], sacc[jt][3]));
        }
        mx0 = fmaxf(mx0, __shfl_xor_sync(0xffffffff, mx0, 1));
        mx0 = fmaxf(mx0, __shfl_xor_sync(0xffffffff, mx0, 2));
        mx1 = fmaxf(mx1, __shfl_xor_sync(0xffffffff, mx1, 1));
        mx1 = fmaxf(mx1, __shfl_xor_sync(0xffffffff, mx1, 2));

        const float m0n = fmaxf(m0, mx0);
        const float m1n = fmaxf(m1, mx1);
        const float a0 = exp2f(m0 - m0n);
        const float a1 = exp2f(m1 - m1n);
        m0 = m0n; m1 = m1n;
        l0 *= a0; l1 *= a1;
#pragma unroll
        for (int d = 0; d < 8; d++) {
            oacc[d][0] *= a0; oacc[d][1] *= a0;
            oacc[d][2] *= a1; oacc[d][3] *= a1;
        }

        // ---- p = exp2(s - m), fp16-rounded; store to Pw; row-sums ----
        float rs0 = 0.f, rs1 = 0.f;
#pragma unroll
        for (int jt = 0; jt < 8; jt++) {
            __half2 hp0 = __floats2half2_rn(exp2f(sacc[jt][0] - m0),
                                            exp2f(sacc[jt][1] - m0));
            __half2 hp1 = __floats2half2_rn(exp2f(sacc[jt][2] - m1),
                                            exp2f(sacc[jt][3] - m1));
            float2 f0 = __half22float2(hp0);
            float2 f1 = __half22float2(hp1);
            rs0 += f0.x + f0.y;
            rs1 += f1.x + f1.y;
            const int pc = 8 * jt + 2 * t;
            *(__half2*)(Pw + g * QPH + pc)       = hp0;
            *(__half2*)(Pw + (g + 8) * QPH + pc) = hp1;
        }
        rs0 += __shfl_xor_sync(0xffffffff, rs0, 1);
        rs0 += __shfl_xor_sync(0xffffffff, rs0, 2);
        rs1 += __shfl_xor_sync(0xffffffff, rs1, 1);
        rs1 += __shfl_xor_sync(0xffffffff, rs1, 2);
        l0 += rs0; l1 += rs1;
        __syncwarp();

        // ---- O += P @ V ----
#pragma unroll
        for (int s = 0; s < 4; s++) {
            uint32_t pa[4];
            LDSM_X4(pa[0], pa[1], pa[2], pa[3], p_lds0 + 32u * s);
#pragma unroll
            for (int dp = 0; dp < 4; dp++) {
                uint32_t r0, r1, r2, r3;
                const uint32_t va = v_lds0 +
                    (uint32_t)((kbase + 16 * s) * VHP * 2) + 32u * dp;
                LDSM_X4T(r0, r1, r2, r3, va);
                uint32_t b0[2] = {r0, r1};
                uint32_t b1[2] = {r2, r3};
                mma_f16(oacc[2 * dp],     pa, b0);
                mma_f16(oacc[2 * dp + 1], pa, b1);
            }
        }
        __syncwarp();
    }

    // ---- normalize + emit DIRECTLY as two fp16 A-image tiles ----
    __syncthreads();                     // all warps done reading Kh/Vh
    __half* stage = Kh;                  // 16 KB staging: tiles kc=0,1
    const float inv0 = 1.f / l0;
    const float inv1 = 1.f / l1;
#pragma unroll
    for (int u = 0; u < 4; u++) {
        __half2 e01 = __floats2half2_rn(oacc[2*u][0]   * inv0, oacc[2*u][1]   * inv0);
        __half2 e23 = __floats2half2_rn(oacc[2*u][2]   * inv1, oacc[2*u][3]   * inv1);
        __half2 e45 = __floats2half2_rn(oacc[2*u+1][0] * inv0, oacc[2*u+1][1] * inv0);
        __half2 e67 = __floats2half2_rn(oacc[2*u+1][2] * inv1, oacc[2*u+1][3] * inv1);
        uint4 pack;
        pack.x = *(uint32_t*)&e01;
        pack.y = *(uint32_t*)&e23;
        pack.z = *(uint32_t*)&e45;
        pack.w = *(uint32_t*)&e67;
        __half* dst = stage + ((u >> 1) << 12) + (((w << 1) + (u & 1)) << 8) + (lane << 3);
        *(uint4*)dst = pack;
    }
    __syncthreads();

    // cooperative coalesced copy of both 8 KB tiles to g_attnH
    {
        const int mt = (b * SS + qb * 128) >> 7;
        const int kc0 = h * 2;
        __half* gdst = g_attnH + ((size_t)(mt * (DD / 32) + kc0) << 12);
        const uint4* src = (const uint4*)stage;
        uint4* dst = (uint4*)gdst;
#pragma unroll
        for (int i = 0; i < 4; i++)
            dst[tid + 256 * i] = src[tid + 256 * i];
    }
}

// ---------------------------------------------------------------------------
extern "C" void kernel_launch(void* const* d_in, const int* in_sizes, int n_in,
                              void* d_out, int out_size)
{
    const float* hidden = (const float*)d_in[0];
    const float* wqkv   = (const float*)d_in[1];
    const float* wo     = (const float*)d_in[2];
    const int*   pos    = (const int*)d_in[4];
    float*       out    = (float*)d_out;

    float  *qkv_p;
    __half *hidH_p, *attnH_p, *wqH_p, *woH_p;
    cudaGetSymbolAddress((void**)&qkv_p,   g_qkv);
    cudaGetSymbolAddress((void**)&hidH_p,  g_hidH);
    cudaGetSymbolAddress((void**)&attnH_p, g_attnH);
    cudaGetSymbolAddress((void**)&wqH_p,   g_wqH);
    cudaGetSymbolAddress((void**)&woH_p,   g_woH);

    cudaFuncSetAttribute(gemm_h,   cudaFuncAttributeMaxDynamicSharedMemorySize, GEMM_SMEM);
    cudaFuncSetAttribute(attn_mma, cudaFuncAttributeMaxDynamicSharedMemorySize, ATTN_SMEM);

    // 0) fused prologue: RoPE table + all operand images (one launch)
    prologue<<<5888, 256>>>(hidden, wqkv, wo, pos);

    // 1) QKV = hidden @ Wqkv^T   [4096, 2304] row-major fp32
    gemm_h<<<dim3(QKVD / 128, NTOK / 128), 256, GEMM_SMEM>>>(hidH_p, wqH_p, qkv_p,
                                                             QKVD, DD / 32);
    // 2) fused RoPE + sliding-window attention -> g_attnH (fp16 A-image, direct)
    attn_mma<<<dim3(SS / 128, BB * HH), 256, ATTN_SMEM>>>();
    // 3) out = attn @ Wo^T       [4096, 768] row-major fp32
    gemm_h<<<dim3(DD / 128, NTOK / 128), 256, GEMM_SMEM>>>(attnH_p, woH_p, out,
                                                           DD, DD / 32);
}